// round 1
// baseline (speedup 1.0000x reference)
#include <cuda_runtime.h>
#include <cuda_bf16.h>
#include <math.h>

// ---------------- problem constants ----------------
#define BB 4
#define LL 2048
#define DMODEL 1024
#define DSTATE 16
#define DCONV 4
#define DINNER 2048
#define M_ROWS (BB*LL)            // 8192

typedef unsigned long long u64;

// ---------------- scratch (device globals; no runtime alloc) ----------------
__device__ float g_xz[(size_t)M_ROWS * (2*DINNER)];   // [8192, 4096]  x@W_in
__device__ float g_xc[(size_t)M_ROWS * DINNER];       // [8192, 2048]  conv+silu
__device__ float g_coef[(size_t)M_ROWS * 48];         // per (b,l): abar[16], bbar[16], c[16]
__device__ float g_yact[(size_t)M_ROWS * DINNER];     // [8192, 2048]  scan output * gate
__device__ float g_WxT[33 * DINNER];                  // W_x transposed [33, 2048]

// ---------------- f32x2 helpers ----------------
__device__ __forceinline__ u64 pack2(float a, float b) {
    u64 r; asm("mov.b64 %0, {%1, %2};" : "=l"(r) : "f"(a), "f"(b)); return r;
}
__device__ __forceinline__ void fma2(u64& d, u64 a, u64 b) {
    asm("fma.rn.f32x2 %0, %1, %2, %0;" : "+l"(d) : "l"(a), "l"(b));
}

// ---------------- GEMM: C[M,N] = A[M,K] @ B[K,N], fp32, f32x2 accumulate ----------------
// 128x128 tile, BK=16, 256 threads, 8x8 per-thread microtile.
__global__ __launch_bounds__(256) void sgemm_f2(
    const float* __restrict__ A, const float* __restrict__ B, float* __restrict__ C,
    int M, int N, int K)
{
    const int BM = 128, BN = 128, BK = 16;
    __shared__ __align__(16) float As[BK][BM];   // transposed A tile
    __shared__ __align__(16) float Bs[BK][BN];

    const int tid  = threadIdx.x;
    const int crow = tid >> 4;          // 0..15
    const int ccol = tid & 15;          // 0..15
    const long brow = (long)blockIdx.y * BM;
    const long bcol = (long)blockIdx.x * BN;

    const int aRow = tid >> 2;          // 0..63
    const int aCol = (tid & 3) << 2;    // 0,4,8,12
    const int bRow = tid >> 5;          // 0..7
    const int bCol = (tid & 31) << 2;   // 0..124

    const float* Ab = A + brow * (long)K;
    const float* Bb = B + bcol;

    u64 acc[8][4];
    #pragma unroll
    for (int m = 0; m < 8; m++)
        #pragma unroll
        for (int j = 0; j < 4; j++) acc[m][j] = 0ull;

    for (int kt = 0; kt < K; kt += BK) {
        #pragma unroll
        for (int i = 0; i < 2; i++) {
            float4 v = *(const float4*)&Ab[(long)(aRow + i*64) * K + kt + aCol];
            As[aCol+0][aRow + i*64] = v.x;
            As[aCol+1][aRow + i*64] = v.y;
            As[aCol+2][aRow + i*64] = v.z;
            As[aCol+3][aRow + i*64] = v.w;
            *(float4*)&Bs[bRow + i*8][bCol] =
                *(const float4*)&Bb[(long)(kt + bRow + i*8) * N + bCol];
        }
        __syncthreads();

        #pragma unroll
        for (int k = 0; k < BK; k++) {
            float regM[8];
            u64 regN[4];
            #pragma unroll
            for (int m = 0; m < 8; m++) regM[m] = As[k][crow*8 + m];
            const u64* bp = (const u64*)&Bs[k][ccol*8];
            #pragma unroll
            for (int j = 0; j < 4; j++) regN[j] = bp[j];
            #pragma unroll
            for (int m = 0; m < 8; m++) {
                u64 m2 = pack2(regM[m], regM[m]);
                #pragma unroll
                for (int j = 0; j < 4; j++) fma2(acc[m][j], m2, regN[j]);
            }
        }
        __syncthreads();
    }

    #pragma unroll
    for (int m = 0; m < 8; m++) {
        long row = brow + crow*8 + m;
        float* cp = &C[row * (long)N + bcol + ccol*8];
        ulonglong2 s0; s0.x = acc[m][0]; s0.y = acc[m][1];
        ulonglong2 s1; s1.x = acc[m][2]; s1.y = acc[m][3];
        *(ulonglong2*)(cp + 0) = s0;
        *(ulonglong2*)(cp + 4) = s1;
    }
}

// ---------------- depthwise causal conv (K=4) + SiLU ----------------
__global__ __launch_bounds__(256) void conv_silu_kernel(
    const float* __restrict__ xz, const float* __restrict__ conv_w,
    const float* __restrict__ conv_b, float* __restrict__ xc)
{
    long idx = (long)blockIdx.x * 256 + threadIdx.x;   // < 4*2048*2048
    int d  = (int)(idx & (DINNER - 1));
    int bl = (int)(idx >> 11);                          // b*L + l
    int l  = bl & (LL - 1);
    int b  = bl >> 11;
    float acc = conv_b[d];
    #pragma unroll
    for (int k = 0; k < DCONV; k++) {
        int lp = l - (DCONV - 1) + k;
        if (lp >= 0)
            acc += xz[((long)(b * LL + lp)) * (2*DINNER) + d] * conv_w[d * DCONV + k];
    }
    float s = acc / (1.0f + expf(-acc));   // silu
    xc[idx] = s;
}

// ---------------- transpose W_x [2048,33] -> [33,2048] ----------------
__global__ void transpose_wx(const float* __restrict__ Wx, float* __restrict__ WxT) {
    int idx = blockIdx.x * 256 + threadIdx.x;
    if (idx < DINNER * 33) {
        int i = idx / 33, j = idx % 33;
        WxT[j * DINNER + i] = Wx[idx];
    }
}

// ---------------- x_dbl = xc @ W_x, then scan coefficients ----------------
// one warp per (b,l) row; block = 4 warps.
__global__ __launch_bounds__(128) void coef_kernel(
    const float* __restrict__ xc, const float* __restrict__ WxT,
    const float* __restrict__ A_log, float* __restrict__ coef)
{
    __shared__ float srow[4][DINNER];
    __shared__ float souts[4][33];
    int warp = threadIdx.x >> 5;
    int lane = threadIdx.x & 31;
    long r = (long)blockIdx.x * 4 + warp;

    const float* row = xc + r * DINNER;
    float* sr = srow[warp];
    for (int i = lane; i < DINNER; i += 32) sr[i] = row[i];
    __syncwarp();

    for (int j = 0; j < 33; j++) {
        const float* w = WxT + j * DINNER;
        float acc = 0.0f;
        #pragma unroll 8
        for (int i = lane; i < DINNER; i += 32) acc += sr[i] * w[i];
        #pragma unroll
        for (int o = 16; o; o >>= 1) acc += __shfl_xor_sync(0xffffffffu, acc, o);
        if (lane == 0) souts[warp][j] = acc;
    }
    __syncwarp();

    if (lane < DSTATE) {
        float v = souts[warp][0];
        float delta = (v > 20.0f) ? v : log1pf(expf(v));   // softplus
        float Aval = -expf(A_log[lane]);
        float abar = expf(delta * Aval);
        float bbar = delta * souts[warp][1 + lane];
        float cval = souts[warp][17 + lane];
        float* o = coef + r * 48;
        o[lane]      = abar;
        o[16 + lane] = bbar;
        o[32 + lane] = cval;
    }
}

// ---------------- selective scan + D skip + SiLU(z) gate ----------------
// one thread per (b,d); 16 states in registers; tile l for smem staging.
#define TL 16
__global__ __launch_bounds__(256) void scan_kernel(
    const float* __restrict__ coef, const float* __restrict__ xz,
    const float* __restrict__ xc, const float* __restrict__ Dp,
    float* __restrict__ yact)
{
    __shared__ float sc[TL * 48];
    __shared__ float sxc[TL][256];
    __shared__ float sz[TL][256];

    int b  = blockIdx.x >> 3;              // 0..3
    int d0 = (blockIdx.x & 7) * 256;
    int tid = threadIdx.x;
    int d = d0 + tid;

    float h[DSTATE];
    #pragma unroll
    for (int n = 0; n < DSTATE; n++) h[n] = 0.0f;
    float Dd = Dp[d];

    for (int t = 0; t < LL / TL; t++) {
        __syncthreads();
        for (int i = tid; i < TL * 48; i += 256)
            sc[i] = coef[((long)b * LL + t * TL) * 48 + i];
        #pragma unroll
        for (int l = 0; l < TL; l++) {
            long row = (long)b * LL + t * TL + l;
            sxc[l][tid] = xc[row * DINNER + d];
            sz[l][tid]  = xz[row * (2*DINNER) + DINNER + d];
        }
        __syncthreads();

        #pragma unroll
        for (int l = 0; l < TL; l++) {
            const float* a = &sc[l * 48];
            float xv = sxc[l][tid];
            float y = 0.0f;
            #pragma unroll
            for (int n = 0; n < DSTATE; n++) {
                h[n] = a[n] * h[n] + a[16 + n] * xv;
                y += h[n] * a[32 + n];
            }
            float zv = sz[l][tid];
            float sg = zv / (1.0f + expf(-zv));
            yact[((long)b * LL + t * TL + l) * DINNER + d] = (y + xv * Dd) * sg;
        }
    }
}

// ---------------- launch ----------------
extern "C" void kernel_launch(void* const* d_in, const int* in_sizes, int n_in,
                              void* d_out, int out_size)
{
    const float* x       = (const float*)d_in[0];
    const float* W_in    = (const float*)d_in[1];
    const float* conv_w  = (const float*)d_in[2];
    const float* conv_b  = (const float*)d_in[3];
    const float* W_x     = (const float*)d_in[4];
    const float* A_log   = (const float*)d_in[5];
    const float* D_param = (const float*)d_in[6];
    const float* W_out   = (const float*)d_in[7];
    float* out = (float*)d_out;

    float *xz, *xc, *coef, *yact, *WxT;
    cudaGetSymbolAddress((void**)&xz,   g_xz);
    cudaGetSymbolAddress((void**)&xc,   g_xc);
    cudaGetSymbolAddress((void**)&coef, g_coef);
    cudaGetSymbolAddress((void**)&yact, g_yact);
    cudaGetSymbolAddress((void**)&WxT,  g_WxT);

    // 1) xz = x @ W_in     [8192,1024]@[1024,4096]
    sgemm_f2<<<dim3((2*DINNER)/128, M_ROWS/128), 256>>>(x, W_in, xz, M_ROWS, 2*DINNER, DMODEL);

    // 2) depthwise conv + silu  -> xc
    conv_silu_kernel<<<(M_ROWS * DINNER) / 256, 256>>>(xz, conv_w, conv_b, xc);

    // 3) W_x transpose (tiny)
    transpose_wx<<<(DINNER * 33 + 255) / 256, 256>>>(W_x, WxT);

    // 4) x_dbl + scan coefficients
    coef_kernel<<<M_ROWS / 4, 128>>>(xc, WxT, A_log, coef);

    // 5) selective scan + skip + gate -> yact
    scan_kernel<<<BB * (DINNER / 256), 256>>>(coef, xz, xc, D_param, yact);

    // 6) out = yact @ W_out   [8192,2048]@[2048,1024]
    sgemm_f2<<<dim3(DMODEL/128, M_ROWS/128), 256>>>(yact, W_out, out, M_ROWS, DMODEL, DINNER);
}

// round 3
// speedup vs baseline: 1.9499x; 1.9499x over previous
#include <cuda_runtime.h>
#include <cuda_bf16.h>
#include <math.h>
#include <stdint.h>

#define BB 4
#define LL 2048
#define DMODEL 1024
#define DSTATE 16
#define DCONV 4
#define DINNER 2048
#define M_ROWS (BB*LL)            // 8192

typedef unsigned long long u64;
typedef unsigned int u32;
typedef __nv_bfloat16 bf16;

// ---------------- scratch (device globals) ----------------
__device__ __align__(16) float g_xz[(size_t)M_ROWS * (2*DINNER)];
__device__ __align__(16) bf16  g_xh[(size_t)M_ROWS * DMODEL];
__device__ __align__(16) bf16  g_xl[(size_t)M_ROWS * DMODEL];
__device__ __align__(16) bf16  g_winT_h[(size_t)(2*DINNER) * DMODEL];
__device__ __align__(16) bf16  g_winT_l[(size_t)(2*DINNER) * DMODEL];
__device__ __align__(16) float g_xc[(size_t)M_ROWS * DINNER];
__device__ __align__(16) bf16  g_xch[(size_t)M_ROWS * DINNER];
__device__ __align__(16) bf16  g_xcl[(size_t)M_ROWS * DINNER];
__device__ __align__(16) bf16  g_wxT_h[64 * DINNER];
__device__ __align__(16) bf16  g_wxT_l[64 * DINNER];
__device__ __align__(16) float g_xdbl[(size_t)M_ROWS * 64];
__device__ __align__(16) float g_coef[(size_t)M_ROWS * 48];
__device__ __align__(16) bf16  g_yh[(size_t)M_ROWS * DINNER];
__device__ __align__(16) bf16  g_yl[(size_t)M_ROWS * DINNER];
__device__ __align__(16) bf16  g_woutT_h[(size_t)DMODEL * DINNER];
__device__ __align__(16) bf16  g_woutT_l[(size_t)DMODEL * DINNER];

// ---------------- PTX helpers (BASE PTX ONLY — no tcgen05 on compute_103) ----------------
__device__ __forceinline__ u32 smem_u32(const void* p) {
    u32 a; asm("{ .reg .u64 t; cvta.to.shared.u64 t, %1; cvt.u32.u64 %0, t; }" : "=r"(a) : "l"(p));
    return a;
}
__device__ __forceinline__ void cp16(u32 dst, const void* src) {
    asm volatile("cp.async.cg.shared.global [%0], [%1], 16;" :: "r"(dst), "l"(src));
}
__device__ __forceinline__ void cp_commit() {
    asm volatile("cp.async.commit_group;" ::: "memory");
}
__device__ __forceinline__ void ldsm4(u32* r, u32 addr) {
    asm volatile("ldmatrix.sync.aligned.m8n8.x4.shared.b16 {%0,%1,%2,%3}, [%4];"
                 : "=r"(r[0]), "=r"(r[1]), "=r"(r[2]), "=r"(r[3]) : "r"(addr));
}
__device__ __forceinline__ void mma16816(float* d, const u32* a, const u32 b0, const u32 b1) {
    asm volatile(
        "mma.sync.aligned.m16n8k16.row.col.f32.bf16.bf16.f32 "
        "{%0,%1,%2,%3}, {%4,%5,%6,%7}, {%8,%9}, {%0,%1,%2,%3};"
        : "+f"(d[0]), "+f"(d[1]), "+f"(d[2]), "+f"(d[3])
        : "r"(a[0]), "r"(a[1]), "r"(a[2]), "r"(a[3]), "r"(b0), "r"(b1));
}

// ---------------- bf16-split HMMA GEMM ----------------
// C[M,N] = (Ah+Al)[M,K] @ (Bh+Bl)^T, B* stored [N,K] K-major.
// Tile 128 x BN, BK=32, padded 80B SMEM rows, cp.async double buffer.
// Warps: 2 (m, 64 rows each) x BN/32 (n, 32 cols each).
#define PITCH 80   // bytes per SMEM row (32 bf16 + 8 pad)

template<int BN>
__global__ __launch_bounds__(BN*2) void gemm_mma(
    const bf16* __restrict__ Ah, const bf16* __restrict__ Al,
    const bf16* __restrict__ Bh, const bf16* __restrict__ Bl,
    float* __restrict__ C, int N, int K)
{
    constexpr int THREADS = BN * 2;
    constexpr int ABYT = 128 * PITCH;          // one A matrix (hi or lo)
    constexpr int BBYT = BN * PITCH;
    constexpr int OFF_AL = ABYT;
    constexpr int OFF_BH = 2 * ABYT;
    constexpr int OFF_BL = 2 * ABYT + BBYT;
    constexpr int STAGE = 2 * ABYT + 2 * BBYT;

    extern __shared__ __align__(16) char smem[];
    const u32 sb = smem_u32(smem);

    const int tid = threadIdx.x;
    const long brow = (long)blockIdx.y * 128;
    const long bcol = (long)blockIdx.x * BN;

    const int wid  = tid >> 5;
    const int lane = tid & 31;
    const int wm = wid & 1;          // 0/1 -> rows [wm*64, wm*64+64)
    const int wn = wid >> 1;         // cols [wn*32, wn*32+32)

    // ldmatrix lane address offsets
    const int a_row  = lane & 15;
    const int a_colb = (lane >> 4) * 16;                       // bytes
    const int q = lane >> 3;
    const int b_n  = (lane & 7) + ((q >> 1) << 3);
    const int b_kb = (q & 1) * 16;                             // bytes

    const u32 aAddrH = sb + (u32)((wm*64 + a_row) * PITCH + a_colb);
    const u32 aAddrL = aAddrH + OFF_AL;
    const u32 bAddrH = sb + OFF_BH + (u32)((wn*32 + b_n) * PITCH + b_kb);
    const u32 bAddrL = bAddrH + (OFF_BL - OFF_BH);

    float acc[4][4][4];
    #pragma unroll
    for (int i = 0; i < 4; i++)
        #pragma unroll
        for (int j = 0; j < 4; j++)
            #pragma unroll
            for (int v = 0; v < 4; v++) acc[i][j][v] = 0.0f;

    const int nst = K >> 5;   // K/32

    // ---- loader ----
    auto load_stage = [&](int s) {
        const u32 base = sb + (s & 1) * STAGE;
        const int kt = s << 5;
        #pragma unroll
        for (int i = tid; i < 512; i += THREADS) {        // A: 128 rows x 4 chunks
            int r = i >> 2, ch = i & 3;
            u32 d = base + (u32)(r * PITCH + ch * 16);
            long g = (brow + r) * (long)K + kt + ch * 8;
            cp16(d, Ah + g);
            cp16(d + OFF_AL, Al + g);
        }
        #pragma unroll
        for (int i = tid; i < BN*4; i += THREADS) {       // B: BN rows x 4 chunks
            int r = i >> 2, ch = i & 3;
            u32 d = base + OFF_BH + (u32)(r * PITCH + ch * 16);
            long g = (bcol + r) * (long)K + kt + ch * 8;
            cp16(d, Bh + g);
            cp16(d + BBYT, Bl + g);
        }
        cp_commit();
    };

    load_stage(0);

    for (int s = 0; s < nst; s++) {
        if (s + 1 < nst) {
            load_stage(s + 1);
            asm volatile("cp.async.wait_group 1;" ::: "memory");
        } else {
            asm volatile("cp.async.wait_group 0;" ::: "memory");
        }
        __syncthreads();

        const u32 boff = (u32)((s & 1) * STAGE);
        #pragma unroll
        for (int kk = 0; kk < 2; kk++) {
            const u32 kadd = kk * 32;   // 16 bf16 = 32 bytes
            u32 bh[2][4], bl[2][4];
            ldsm4(bh[0], bAddrH + boff + kadd);
            ldsm4(bh[1], bAddrH + boff + kadd + 16*PITCH);
            ldsm4(bl[0], bAddrL + boff + kadd);
            ldsm4(bl[1], bAddrL + boff + kadd + 16*PITCH);
            #pragma unroll
            for (int mt = 0; mt < 4; mt++) {
                u32 ah[4], al[4];
                ldsm4(ah, aAddrH + boff + kadd + (u32)(mt*16*PITCH));
                ldsm4(al, aAddrL + boff + kadd + (u32)(mt*16*PITCH));
                #pragma unroll
                for (int nt = 0; nt < 4; nt++) {
                    const int p = nt >> 1, h = nt & 1;
                    mma16816(acc[mt][nt], ah, bh[p][2*h], bh[p][2*h+1]);
                    mma16816(acc[mt][nt], ah, bl[p][2*h], bl[p][2*h+1]);
                    mma16816(acc[mt][nt], al, bh[p][2*h], bh[p][2*h+1]);
                }
            }
        }
        __syncthreads();
    }

    // ---- epilogue ----
    #pragma unroll
    for (int mt = 0; mt < 4; mt++) {
        long r0 = brow + wm*64 + mt*16 + (lane >> 2);
        long cc = bcol + wn*32 + ((lane & 3) << 1);
        #pragma unroll
        for (int nt = 0; nt < 4; nt++) {
            float2 v0 = make_float2(acc[mt][nt][0], acc[mt][nt][1]);
            float2 v1 = make_float2(acc[mt][nt][2], acc[mt][nt][3]);
            *(float2*)&C[r0 * N + cc + nt*8]       = v0;
            *(float2*)&C[(r0+8) * N + cc + nt*8]   = v1;
        }
    }
}

// ---------------- split fp32 -> bf16 hi/lo ----------------
__global__ __launch_bounds__(256) void split_kernel(
    const float* __restrict__ src, bf16* __restrict__ hi, bf16* __restrict__ lo, int n)
{
    int i = blockIdx.x * 256 + threadIdx.x;
    if (i < n) {
        float v = src[i];
        bf16 h = __float2bfloat16_rn(v);
        hi[i] = h;
        lo[i] = __float2bfloat16_rn(v - __bfloat162float(h));
    }
}

// ---------------- transpose [R,C] -> [Cpad,R] + split ----------------
__global__ void transpose_split(
    const float* __restrict__ src, bf16* __restrict__ hi, bf16* __restrict__ lo,
    int R, int C, int Cpad)
{
    __shared__ float t[32][33];
    int c0 = blockIdx.x * 32, r0 = blockIdx.y * 32;
    int tx = threadIdx.x, ty = threadIdx.y;
    #pragma unroll
    for (int i = 0; i < 32; i += 8) {
        int c = c0 + tx;
        float v = (c < C) ? src[(long)(r0 + ty + i) * C + c] : 0.0f;
        t[ty + i][tx] = v;
    }
    __syncthreads();
    #pragma unroll
    for (int i = 0; i < 32; i += 8) {
        int oc = c0 + ty + i;
        if (oc < Cpad) {
            float v = t[tx][ty + i];
            bf16 h = __float2bfloat16_rn(v);
            hi[(long)oc * R + r0 + tx] = h;
            lo[(long)oc * R + r0 + tx] = __float2bfloat16_rn(v - __bfloat162float(h));
        }
    }
}

// ---------------- depthwise causal conv (K=4) + SiLU ----------------
__global__ __launch_bounds__(256) void conv_silu_kernel(
    const float* __restrict__ xz, const float* __restrict__ conv_w,
    const float* __restrict__ conv_b, float* __restrict__ xc,
    bf16* __restrict__ xch, bf16* __restrict__ xcl)
{
    long idx = (long)blockIdx.x * 256 + threadIdx.x;
    int d  = (int)(idx & (DINNER - 1));
    int bl = (int)(idx >> 11);
    int l  = bl & (LL - 1);
    int b  = bl >> 11;
    float acc = conv_b[d];
    #pragma unroll
    for (int k = 0; k < DCONV; k++) {
        int lp = l - (DCONV - 1) + k;
        if (lp >= 0)
            acc += xz[((long)(b * LL + lp)) * (2*DINNER) + d] * conv_w[d * DCONV + k];
    }
    float s = acc / (1.0f + expf(-acc));
    xc[idx] = s;
    bf16 h = __float2bfloat16_rn(s);
    xch[idx] = h;
    xcl[idx] = __float2bfloat16_rn(s - __bfloat162float(h));
}

// ---------------- coef finisher ----------------
__global__ __launch_bounds__(128) void coef_finish(
    const float* __restrict__ xdbl, const float* __restrict__ A_log, float* __restrict__ coef)
{
    int tid = threadIdx.x;
    int rloc = tid >> 4, n = tid & 15;
    long r = (long)blockIdx.x * 8 + rloc;
    const float* xr = xdbl + r * 64;
    float v = xr[0];
    float delta = (v > 20.0f) ? v : log1pf(expf(v));
    float abar = expf(delta * (-expf(A_log[n])));
    float bbar = delta * xr[1 + n];
    float cval = xr[17 + n];
    float* o = coef + r * 48;
    o[n] = abar; o[16 + n] = bbar; o[32 + n] = cval;
}

// ---------------- selective scan + D skip + SiLU(z) gate -> bf16 split ----------------
#define TL 16
__global__ __launch_bounds__(256) void scan_kernel(
    const float* __restrict__ coef, const float* __restrict__ xz,
    const float* __restrict__ xc, const float* __restrict__ Dp,
    bf16* __restrict__ yh, bf16* __restrict__ yl)
{
    __shared__ float sc[TL * 48];
    __shared__ float sxc[TL][256];
    __shared__ float sz[TL][256];

    int b  = blockIdx.x >> 3;
    int d0 = (blockIdx.x & 7) * 256;
    int tid = threadIdx.x;
    int d = d0 + tid;

    float h[DSTATE];
    #pragma unroll
    for (int n = 0; n < DSTATE; n++) h[n] = 0.0f;
    float Dd = Dp[d];

    for (int t = 0; t < LL / TL; t++) {
        __syncthreads();
        for (int i = tid; i < TL * 48; i += 256)
            sc[i] = coef[((long)b * LL + t * TL) * 48 + i];
        #pragma unroll
        for (int l = 0; l < TL; l++) {
            long row = (long)b * LL + t * TL + l;
            sxc[l][tid] = xc[row * DINNER + d];
            sz[l][tid]  = xz[row * (2*DINNER) + DINNER + d];
        }
        __syncthreads();

        #pragma unroll
        for (int l = 0; l < TL; l++) {
            const float* a = &sc[l * 48];
            float xv = sxc[l][tid];
            float y = 0.0f;
            #pragma unroll
            for (int n = 0; n < DSTATE; n++) {
                h[n] = a[n] * h[n] + a[16 + n] * xv;
                y += h[n] * a[32 + n];
            }
            float zv = sz[l][tid];
            float sg = zv / (1.0f + expf(-zv));
            float val = (y + xv * Dd) * sg;
            long idx = ((long)b * LL + t * TL + l) * DINNER + d;
            bf16 hv = __float2bfloat16_rn(val);
            yh[idx] = hv;
            yl[idx] = __float2bfloat16_rn(val - __bfloat162float(hv));
        }
    }
}

// ---------------- launch ----------------
extern "C" void kernel_launch(void* const* d_in, const int* in_sizes, int n_in,
                              void* d_out, int out_size)
{
    const float* x       = (const float*)d_in[0];
    const float* W_in    = (const float*)d_in[1];
    const float* conv_w  = (const float*)d_in[2];
    const float* conv_b  = (const float*)d_in[3];
    const float* W_x     = (const float*)d_in[4];
    const float* A_log   = (const float*)d_in[5];
    const float* D_param = (const float*)d_in[6];
    const float* W_out   = (const float*)d_in[7];
    float* out = (float*)d_out;

    float *xz, *xc, *coefp, *xdbl;
    bf16 *xh, *xl, *winh, *winl, *xch, *xcl, *wxh, *wxl, *yh, *yl, *woh, *wol;
    cudaGetSymbolAddress((void**)&xz,   g_xz);
    cudaGetSymbolAddress((void**)&xc,   g_xc);
    cudaGetSymbolAddress((void**)&coefp,g_coef);
    cudaGetSymbolAddress((void**)&xdbl, g_xdbl);
    cudaGetSymbolAddress((void**)&xh,   g_xh);
    cudaGetSymbolAddress((void**)&xl,   g_xl);
    cudaGetSymbolAddress((void**)&winh, g_winT_h);
    cudaGetSymbolAddress((void**)&winl, g_winT_l);
    cudaGetSymbolAddress((void**)&xch,  g_xch);
    cudaGetSymbolAddress((void**)&xcl,  g_xcl);
    cudaGetSymbolAddress((void**)&wxh,  g_wxT_h);
    cudaGetSymbolAddress((void**)&wxl,  g_wxT_l);
    cudaGetSymbolAddress((void**)&yh,   g_yh);
    cudaGetSymbolAddress((void**)&yl,   g_yl);
    cudaGetSymbolAddress((void**)&woh,  g_woutT_h);
    cudaGetSymbolAddress((void**)&wol,  g_woutT_l);

    // stage = 2*A(128*80) + 2*B(BN*80); double buffered
    const int SMEM128 = 2 * (2*128*80 + 2*128*80);   // 81920
    const int SMEM64  = 2 * (2*128*80 + 2*64*80);    // 61440
    cudaFuncSetAttribute(gemm_mma<128>, cudaFuncAttributeMaxDynamicSharedMemorySize, SMEM128);
    cudaFuncSetAttribute(gemm_mma<64>,  cudaFuncAttributeMaxDynamicSharedMemorySize, SMEM64);

    // 1) splits / transposed weight splits
    split_kernel<<<(M_ROWS*DMODEL)/256, 256>>>(x, xh, xl, M_ROWS*DMODEL);
    transpose_split<<<dim3(4096/32, 1024/32), dim3(32,8)>>>(W_in,  winh, winl, 1024, 4096, 4096);
    transpose_split<<<dim3(1024/32, 2048/32), dim3(32,8)>>>(W_out, woh,  wol,  2048, 1024, 1024);
    transpose_split<<<dim3(64/32,   2048/32), dim3(32,8)>>>(W_x,   wxh,  wxl,  2048, 33,   64);

    // 2) xz = x @ W_in   [8192,1024]@[1024,4096]
    gemm_mma<128><<<dim3(4096/128, 8192/128), 256, SMEM128>>>(xh, xl, winh, winl, xz, 4096, 1024);

    // 3) conv + silu -> xc (fp32 + bf16 split)
    conv_silu_kernel<<<(M_ROWS*DINNER)/256, 256>>>(xz, conv_w, conv_b, xc, xch, xcl);

    // 4) x_dbl = xc @ W_x (padded N=64)
    gemm_mma<64><<<dim3(1, 8192/128), 128, SMEM64>>>(xch, xcl, wxh, wxl, xdbl, 64, 2048);

    // 5) coefficients
    coef_finish<<<M_ROWS/8, 128>>>(xdbl, A_log, coefp);

    // 6) scan + skip + gate -> y (bf16 split)
    scan_kernel<<<BB * (DINNER/256), 256>>>(coefp, xz, xc, D_param, yh, yl);

    // 7) out = y @ W_out  [8192,2048]@[2048,1024]
    gemm_mma<128><<<dim3(1024/128, 8192/128), 256, SMEM128>>>(yh, yl, woh, wol, out, 1024, 2048);
}

// round 4
// speedup vs baseline: 2.2577x; 1.1579x over previous
#include <cuda_runtime.h>
#include <cuda_bf16.h>
#include <cuda_fp16.h>
#include <math.h>
#include <stdint.h>

#define BB 4
#define LL 2048
#define DMODEL 1024
#define DSTATE 16
#define DCONV 4
#define DINNER 2048
#define M_ROWS (BB*LL)            // 8192

typedef unsigned int u32;
typedef __nv_bfloat16 bf16;
typedef uint16_t u16;

// ---------------- scratch (device globals) ----------------
__device__ __align__(16) float g_xz[(size_t)M_ROWS * (2*DINNER)];
__device__ __align__(16) __half g_xh[(size_t)M_ROWS * DMODEL];
__device__ __align__(16) __half g_xl[(size_t)M_ROWS * DMODEL];
__device__ __align__(16) __half g_winT[(size_t)(2*DINNER) * DMODEL];   // fp16 hi only
__device__ __align__(16) float g_xc[(size_t)M_ROWS * DINNER];
__device__ __align__(16) bf16  g_xch[(size_t)M_ROWS * DINNER];
__device__ __align__(16) bf16  g_xcl[(size_t)M_ROWS * DINNER];
__device__ __align__(16) bf16  g_wxT_h[64 * DINNER];
__device__ __align__(16) bf16  g_wxT_l[64 * DINNER];
__device__ __align__(16) float g_xdbl[(size_t)M_ROWS * 64];
__device__ __align__(16) float g_coef[(size_t)M_ROWS * 48];
__device__ __align__(16) __half g_yh[(size_t)M_ROWS * DINNER];
__device__ __align__(16) __half g_yl[(size_t)M_ROWS * DINNER];
__device__ __align__(16) __half g_woutT[(size_t)DMODEL * DINNER];      // fp16 hi only

// ---------------- PTX helpers (BASE PTX ONLY) ----------------
__device__ __forceinline__ u32 smem_u32(const void* p) {
    u32 a; asm("{ .reg .u64 t; cvta.to.shared.u64 t, %1; cvt.u32.u64 %0, t; }" : "=r"(a) : "l"(p));
    return a;
}
__device__ __forceinline__ void cp16(u32 dst, const void* src) {
    asm volatile("cp.async.cg.shared.global [%0], [%1], 16;" :: "r"(dst), "l"(src));
}
__device__ __forceinline__ void cp_commit() {
    asm volatile("cp.async.commit_group;" ::: "memory");
}
__device__ __forceinline__ void ldsm4(u32* r, u32 addr) {
    asm volatile("ldmatrix.sync.aligned.m8n8.x4.shared.b16 {%0,%1,%2,%3}, [%4];"
                 : "=r"(r[0]), "=r"(r[1]), "=r"(r[2]), "=r"(r[3]) : "r"(addr));
}
__device__ __forceinline__ void mma_bf16(float* d, const u32* a, const u32 b0, const u32 b1) {
    asm volatile(
        "mma.sync.aligned.m16n8k16.row.col.f32.bf16.bf16.f32 "
        "{%0,%1,%2,%3}, {%4,%5,%6,%7}, {%8,%9}, {%0,%1,%2,%3};"
        : "+f"(d[0]), "+f"(d[1]), "+f"(d[2]), "+f"(d[3])
        : "r"(a[0]), "r"(a[1]), "r"(a[2]), "r"(a[3]), "r"(b0), "r"(b1));
}
__device__ __forceinline__ void mma_f16(float* d, const u32* a, const u32 b0, const u32 b1) {
    asm volatile(
        "mma.sync.aligned.m16n8k16.row.col.f32.f16.f16.f32 "
        "{%0,%1,%2,%3}, {%4,%5,%6,%7}, {%8,%9}, {%0,%1,%2,%3};"
        : "+f"(d[0]), "+f"(d[1]), "+f"(d[2]), "+f"(d[3])
        : "r"(a[0]), "r"(a[1]), "r"(a[2]), "r"(a[3]), "r"(b0), "r"(b1));
}

// ---------------- split HMMA GEMM ----------------
// C[M,N] = A[M,K] @ B[N,K]^T (K-major B).
// TWO_PROD: fp16, A split hi/lo, B hi only -> 2 MMAs per frag pair.
// !TWO_PROD: bf16, A and B split hi/lo -> 3 MMAs.
// Tile 128 x BN, BK=32, 3-stage cp.async ring, 1 sync per stage.
#define PITCH 80   // bytes per SMEM row (32 halfwords + 8B pad)

template<int BN, bool TWO_PROD>
__global__ __launch_bounds__(BN*2, 2) void gemm_mma(
    const u16* __restrict__ Ah, const u16* __restrict__ Al,
    const u16* __restrict__ Bh, const u16* __restrict__ Bl,
    float* __restrict__ C, int N, int K)
{
    constexpr int THREADS = BN * 2;
    constexpr int ABYT = 128 * PITCH;
    constexpr int BBYT = BN * PITCH;
    constexpr int OFF_AL = ABYT;
    constexpr int OFF_BH = 2 * ABYT;
    constexpr int OFF_BL = 2 * ABYT + BBYT;
    constexpr int STAGE = TWO_PROD ? (2*ABYT + BBYT) : (2*ABYT + 2*BBYT);

    extern __shared__ __align__(16) char smem[];
    const u32 sb = smem_u32(smem);

    const int tid = threadIdx.x;
    const long brow = (long)blockIdx.y * 128;
    const long bcol = (long)blockIdx.x * BN;

    const int wid  = tid >> 5;
    const int lane = tid & 31;
    const int wm = wid & 1;
    const int wn = wid >> 1;

    const int a_row  = lane & 15;
    const int a_colb = (lane >> 4) * 16;
    const int q = lane >> 3;
    const int b_n  = (lane & 7) + ((q >> 1) << 3);
    const int b_kb = (q & 1) * 16;

    const u32 aAddrH = sb + (u32)((wm*64 + a_row) * PITCH + a_colb);
    const u32 aAddrL = aAddrH + OFF_AL;
    const u32 bAddrH = sb + OFF_BH + (u32)((wn*32 + b_n) * PITCH + b_kb);
    const u32 bAddrL = bAddrH + BBYT;

    float acc[4][4][4];
    #pragma unroll
    for (int i = 0; i < 4; i++)
        #pragma unroll
        for (int j = 0; j < 4; j++)
            #pragma unroll
            for (int v = 0; v < 4; v++) acc[i][j][v] = 0.0f;

    const int nst = K >> 5;

    auto load_stage = [&](int s) {
        const u32 base = sb + (u32)((s % 3) * STAGE);
        const int kt = s << 5;
        #pragma unroll
        for (int i = tid; i < 512; i += THREADS) {
            int r = i >> 2, ch = i & 3;
            u32 d = base + (u32)(r * PITCH + ch * 16);
            long g = (brow + r) * (long)K + kt + ch * 8;
            cp16(d, Ah + g);
            cp16(d + OFF_AL, Al + g);
        }
        #pragma unroll
        for (int i = tid; i < BN*4; i += THREADS) {
            int r = i >> 2, ch = i & 3;
            u32 d = base + OFF_BH + (u32)(r * PITCH + ch * 16);
            long g = (bcol + r) * (long)K + kt + ch * 8;
            cp16(d, Bh + g);
            if (!TWO_PROD) cp16(d + BBYT, Bl + g);
        }
        cp_commit();
    };

    load_stage(0);
    load_stage(1);

    for (int s = 0; s < nst; s++) {
        if (s + 1 < nst) asm volatile("cp.async.wait_group 1;" ::: "memory");
        else             asm volatile("cp.async.wait_group 0;" ::: "memory");
        __syncthreads();
        if (s + 2 < nst) load_stage(s + 2);   // writes buf (s+2)%3 = (s-1)%3, freed by the sync

        const u32 boff = (u32)((s % 3) * STAGE);
        #pragma unroll
        for (int kk = 0; kk < 2; kk++) {
            const u32 kadd = kk * 32;
            if (TWO_PROD) {
                u32 bh[2][4];
                ldsm4(bh[0], bAddrH + boff + kadd);
                ldsm4(bh[1], bAddrH + boff + kadd + 16*PITCH);
                #pragma unroll
                for (int mt = 0; mt < 4; mt++) {
                    u32 ah[4], al[4];
                    ldsm4(ah, aAddrH + boff + kadd + (u32)(mt*16*PITCH));
                    ldsm4(al, aAddrL + boff + kadd + (u32)(mt*16*PITCH));
                    #pragma unroll
                    for (int nt = 0; nt < 4; nt++) {
                        const int p = nt >> 1, h = nt & 1;
                        mma_f16(acc[mt][nt], ah, bh[p][2*h], bh[p][2*h+1]);
                        mma_f16(acc[mt][nt], al, bh[p][2*h], bh[p][2*h+1]);
                    }
                }
            } else {
                u32 bh[2][4], bl[2][4];
                ldsm4(bh[0], bAddrH + boff + kadd);
                ldsm4(bh[1], bAddrH + boff + kadd + 16*PITCH);
                ldsm4(bl[0], bAddrL + boff + kadd);
                ldsm4(bl[1], bAddrL + boff + kadd + 16*PITCH);
                #pragma unroll
                for (int mt = 0; mt < 4; mt++) {
                    u32 ah[4], al[4];
                    ldsm4(ah, aAddrH + boff + kadd + (u32)(mt*16*PITCH));
                    ldsm4(al, aAddrL + boff + kadd + (u32)(mt*16*PITCH));
                    #pragma unroll
                    for (int nt = 0; nt < 4; nt++) {
                        const int p = nt >> 1, h = nt & 1;
                        mma_bf16(acc[mt][nt], ah, bh[p][2*h], bh[p][2*h+1]);
                        mma_bf16(acc[mt][nt], ah, bl[p][2*h], bl[p][2*h+1]);
                        mma_bf16(acc[mt][nt], al, bh[p][2*h], bh[p][2*h+1]);
                    }
                }
            }
        }
        __syncthreads();   // compute(s) done before buf s%3 reload at s+3
    }

    #pragma unroll
    for (int mt = 0; mt < 4; mt++) {
        long r0 = brow + wm*64 + mt*16 + (lane >> 2);
        long cc = bcol + wn*32 + ((lane & 3) << 1);
        #pragma unroll
        for (int nt = 0; nt < 4; nt++) {
            float2 v0 = make_float2(acc[mt][nt][0], acc[mt][nt][1]);
            float2 v1 = make_float2(acc[mt][nt][2], acc[mt][nt][3]);
            *(float2*)&C[r0 * N + cc + nt*8]     = v0;
            *(float2*)&C[(r0+8) * N + cc + nt*8] = v1;
        }
    }
}

// ---------------- split fp32 -> fp16 hi/lo ----------------
__global__ __launch_bounds__(256) void split_f16(
    const float* __restrict__ src, __half* __restrict__ hi, __half* __restrict__ lo, int n)
{
    int i = blockIdx.x * 256 + threadIdx.x;
    if (i < n) {
        float v = src[i];
        __half h = __float2half_rn(v);
        hi[i] = h;
        lo[i] = __float2half_rn(v - __half2float(h));
    }
}

// ---------------- transpose [R,C] -> [C,R] as fp16 (hi only) ----------------
__global__ void transpose_f16(
    const float* __restrict__ src, __half* __restrict__ dst, int R, int C)
{
    __shared__ float t[32][33];
    int c0 = blockIdx.x * 32, r0 = blockIdx.y * 32;
    int tx = threadIdx.x, ty = threadIdx.y;
    #pragma unroll
    for (int i = 0; i < 32; i += 8)
        t[ty + i][tx] = src[(long)(r0 + ty + i) * C + c0 + tx];
    __syncthreads();
    #pragma unroll
    for (int i = 0; i < 32; i += 8)
        dst[(long)(c0 + ty + i) * R + r0 + tx] = __float2half_rn(t[tx][ty + i]);
}

// ---------------- transpose [R,C] -> [Cpad,R] + bf16 hi/lo split ----------------
__global__ void transpose_split_bf16(
    const float* __restrict__ src, bf16* __restrict__ hi, bf16* __restrict__ lo,
    int R, int C, int Cpad)
{
    __shared__ float t[32][33];
    int c0 = blockIdx.x * 32, r0 = blockIdx.y * 32;
    int tx = threadIdx.x, ty = threadIdx.y;
    #pragma unroll
    for (int i = 0; i < 32; i += 8) {
        int c = c0 + tx;
        float v = (c < C) ? src[(long)(r0 + ty + i) * C + c] : 0.0f;
        t[ty + i][tx] = v;
    }
    __syncthreads();
    #pragma unroll
    for (int i = 0; i < 32; i += 8) {
        int oc = c0 + ty + i;
        if (oc < Cpad) {
            float v = t[tx][ty + i];
            bf16 h = __float2bfloat16_rn(v);
            hi[(long)oc * R + r0 + tx] = h;
            lo[(long)oc * R + r0 + tx] = __float2bfloat16_rn(v - __bfloat162float(h));
        }
    }
}

// ---------------- depthwise causal conv (K=4) + SiLU ----------------
__global__ __launch_bounds__(256) void conv_silu_kernel(
    const float* __restrict__ xz, const float* __restrict__ conv_w,
    const float* __restrict__ conv_b, float* __restrict__ xc,
    bf16* __restrict__ xch, bf16* __restrict__ xcl)
{
    long idx = (long)blockIdx.x * 256 + threadIdx.x;
    int d  = (int)(idx & (DINNER - 1));
    int bl = (int)(idx >> 11);
    int l  = bl & (LL - 1);
    int b  = bl >> 11;
    float acc = conv_b[d];
    #pragma unroll
    for (int k = 0; k < DCONV; k++) {
        int lp = l - (DCONV - 1) + k;
        if (lp >= 0)
            acc += xz[((long)(b * LL + lp)) * (2*DINNER) + d] * conv_w[d * DCONV + k];
    }
    float s = acc / (1.0f + expf(-acc));
    xc[idx] = s;
    bf16 h = __float2bfloat16_rn(s);
    xch[idx] = h;
    xcl[idx] = __float2bfloat16_rn(s - __bfloat162float(h));
}

// ---------------- coef finisher ----------------
__global__ __launch_bounds__(128) void coef_finish(
    const float* __restrict__ xdbl, const float* __restrict__ A_log, float* __restrict__ coef)
{
    int tid = threadIdx.x;
    int rloc = tid >> 4, n = tid & 15;
    long r = (long)blockIdx.x * 8 + rloc;
    const float* xr = xdbl + r * 64;
    float v = xr[0];
    float delta = (v > 20.0f) ? v : log1pf(expf(v));
    float abar = expf(delta * (-expf(A_log[n])));
    float bbar = delta * xr[1 + n];
    float cval = xr[17 + n];
    float* o = coef + r * 48;
    o[n] = abar; o[16 + n] = bbar; o[32 + n] = cval;
}

// ---------------- selective scan + D skip + SiLU(z) gate -> fp16 split ----------------
#define TL 16
__global__ __launch_bounds__(256) void scan_kernel(
    const float* __restrict__ coef, const float* __restrict__ xz,
    const float* __restrict__ xc, const float* __restrict__ Dp,
    __half* __restrict__ yh, __half* __restrict__ yl)
{
    __shared__ float sc[TL * 48];
    __shared__ float sxc[TL][256];
    __shared__ float sz[TL][256];

    int b  = blockIdx.x >> 3;
    int d0 = (blockIdx.x & 7) * 256;
    int tid = threadIdx.x;
    int d = d0 + tid;

    float h[DSTATE];
    #pragma unroll
    for (int n = 0; n < DSTATE; n++) h[n] = 0.0f;
    float Dd = Dp[d];

    for (int t = 0; t < LL / TL; t++) {
        __syncthreads();
        for (int i = tid; i < TL * 48; i += 256)
            sc[i] = coef[((long)b * LL + t * TL) * 48 + i];
        #pragma unroll
        for (int l = 0; l < TL; l++) {
            long row = (long)b * LL + t * TL + l;
            sxc[l][tid] = xc[row * DINNER + d];
            sz[l][tid]  = xz[row * (2*DINNER) + DINNER + d];
        }
        __syncthreads();

        #pragma unroll
        for (int l = 0; l < TL; l++) {
            const float* a = &sc[l * 48];
            float xv = sxc[l][tid];
            float y = 0.0f;
            #pragma unroll
            for (int n = 0; n < DSTATE; n++) {
                h[n] = a[n] * h[n] + a[16 + n] * xv;
                y += h[n] * a[32 + n];
            }
            float zv = sz[l][tid];
            float sg = zv / (1.0f + expf(-zv));
            float val = (y + xv * Dd) * sg;
            long idx = ((long)b * LL + t * TL + l) * DINNER + d;
            __half hv = __float2half_rn(val);
            yh[idx] = hv;
            yl[idx] = __float2half_rn(val - __half2float(hv));
        }
    }
}

// ---------------- launch ----------------
extern "C" void kernel_launch(void* const* d_in, const int* in_sizes, int n_in,
                              void* d_out, int out_size)
{
    const float* x       = (const float*)d_in[0];
    const float* W_in    = (const float*)d_in[1];
    const float* conv_w  = (const float*)d_in[2];
    const float* conv_b  = (const float*)d_in[3];
    const float* W_x     = (const float*)d_in[4];
    const float* A_log   = (const float*)d_in[5];
    const float* D_param = (const float*)d_in[6];
    const float* W_out   = (const float*)d_in[7];
    float* out = (float*)d_out;

    float *xz, *xc, *coefp, *xdbl;
    __half *xh, *xl, *winT, *woutT, *yh, *yl;
    bf16 *xch, *xcl, *wxh, *wxl;
    cudaGetSymbolAddress((void**)&xz,   g_xz);
    cudaGetSymbolAddress((void**)&xc,   g_xc);
    cudaGetSymbolAddress((void**)&coefp,g_coef);
    cudaGetSymbolAddress((void**)&xdbl, g_xdbl);
    cudaGetSymbolAddress((void**)&xh,   g_xh);
    cudaGetSymbolAddress((void**)&xl,   g_xl);
    cudaGetSymbolAddress((void**)&winT, g_winT);
    cudaGetSymbolAddress((void**)&woutT,g_woutT);
    cudaGetSymbolAddress((void**)&xch,  g_xch);
    cudaGetSymbolAddress((void**)&xcl,  g_xcl);
    cudaGetSymbolAddress((void**)&wxh,  g_wxT_h);
    cudaGetSymbolAddress((void**)&wxl,  g_wxT_l);
    cudaGetSymbolAddress((void**)&yh,   g_yh);
    cudaGetSymbolAddress((void**)&yl,   g_yl);

    // 3-stage ring: 2P stage = 2*128*80 + 128*80 = 30720 ; 3P(BN=64) = 2*128*80 + 2*64*80 = 30720
    const int SMEM = 3 * 30720;   // 92160
    cudaFuncSetAttribute((const void*)gemm_mma<128,true>,  cudaFuncAttributeMaxDynamicSharedMemorySize, SMEM);
    cudaFuncSetAttribute((const void*)gemm_mma<64,false>,  cudaFuncAttributeMaxDynamicSharedMemorySize, SMEM);

    // 1) operand prep
    split_f16<<<(M_ROWS*DMODEL)/256, 256>>>(x, xh, xl, M_ROWS*DMODEL);
    transpose_f16<<<dim3(4096/32, 1024/32), dim3(32,8)>>>(W_in,  winT,  1024, 4096);
    transpose_f16<<<dim3(1024/32, 2048/32), dim3(32,8)>>>(W_out, woutT, 2048, 1024);
    transpose_split_bf16<<<dim3(64/32, 2048/32), dim3(32,8)>>>(W_x, wxh, wxl, 2048, 33, 64);

    // 2) xz = x @ W_in   (fp16 2-product)
    gemm_mma<128,true><<<dim3(4096/128, 8192/128), 256, SMEM>>>(
        (const u16*)xh, (const u16*)xl, (const u16*)winT, nullptr, xz, 4096, 1024);

    // 3) conv + silu -> xc (fp32 + bf16 split)
    conv_silu_kernel<<<(M_ROWS*DINNER)/256, 256>>>(xz, conv_w, conv_b, xc, xch, xcl);

    // 4) x_dbl = xc @ W_x (bf16 3-product, padded N=64)
    gemm_mma<64,false><<<dim3(1, 8192/128), 128, SMEM>>>(
        (const u16*)xch, (const u16*)xcl, (const u16*)wxh, (const u16*)wxl, xdbl, 64, 2048);

    // 5) coefficients
    coef_finish<<<M_ROWS/8, 128>>>(xdbl, A_log, coefp);

    // 6) scan + skip + gate -> y (fp16 split)
    scan_kernel<<<BB * (DINNER/256), 256>>>(coefp, xz, xc, D_param, yh, yl);

    // 7) out = y @ W_out  (fp16 2-product)
    gemm_mma<128,true><<<dim3(1024/128, 8192/128), 256, SMEM>>>(
        (const u16*)yh, (const u16*)yl, (const u16*)woutT, nullptr, out, 1024, 2048);
}

// round 5
// speedup vs baseline: 3.6114x; 1.5995x over previous
#include <cuda_runtime.h>
#include <cuda_bf16.h>
#include <cuda_fp16.h>
#include <math.h>
#include <stdint.h>

#define BB 4
#define LL 2048
#define DMODEL 1024
#define DSTATE 16
#define DCONV 4
#define DINNER 2048
#define M_ROWS (BB*LL)            // 8192
#define NCH 16                    // chunks per sequence
#define CHL 128                   // chunk length

typedef unsigned int u32;
typedef unsigned long long u64;
typedef __nv_bfloat16 bf16;
typedef uint16_t u16;

// ---------------- scratch (device globals) ----------------
__device__ __align__(16) float g_xz[(size_t)M_ROWS * (2*DINNER)];
__device__ __align__(16) __half g_xh[(size_t)M_ROWS * DMODEL];
__device__ __align__(16) __half g_xl[(size_t)M_ROWS * DMODEL];
__device__ __align__(16) __half g_winT[(size_t)(2*DINNER) * DMODEL];
__device__ __align__(16) float g_xc[(size_t)M_ROWS * DINNER];
__device__ __align__(16) bf16  g_xch[(size_t)M_ROWS * DINNER];
__device__ __align__(16) bf16  g_xcl[(size_t)M_ROWS * DINNER];
__device__ __align__(16) bf16  g_wxT_h[64 * DINNER];
__device__ __align__(16) bf16  g_wxT_l[64 * DINNER];
__device__ __align__(16) float g_xdbl[(size_t)M_ROWS * 64];
__device__ __align__(16) float g_coef[(size_t)M_ROWS * 48];
__device__ __align__(16) float g_pc[(size_t)M_ROWS * DSTATE];          // cumprod(a)*C
__device__ __align__(16) float g_ptot[BB * NCH * DSTATE];
__device__ __align__(16) float g_hend[(size_t)BB * NCH * DINNER * DSTATE];
__device__ __align__(16) float g_hstart[(size_t)BB * NCH * DINNER * DSTATE];
__device__ __align__(16) __half g_yh[(size_t)M_ROWS * DINNER];
__device__ __align__(16) __half g_woutT[(size_t)DMODEL * DINNER];

// ---------------- PTX helpers (BASE PTX ONLY) ----------------
__device__ __forceinline__ u32 smem_u32(const void* p) {
    u32 a; asm("{ .reg .u64 t; cvta.to.shared.u64 t, %1; cvt.u32.u64 %0, t; }" : "=r"(a) : "l"(p));
    return a;
}
__device__ __forceinline__ void cp16(u32 dst, const void* src) {
    asm volatile("cp.async.cg.shared.global [%0], [%1], 16;" :: "r"(dst), "l"(src));
}
__device__ __forceinline__ void cp_commit() {
    asm volatile("cp.async.commit_group;" ::: "memory");
}
__device__ __forceinline__ void ldsm4(u32* r, u32 addr) {
    asm volatile("ldmatrix.sync.aligned.m8n8.x4.shared.b16 {%0,%1,%2,%3}, [%4];"
                 : "=r"(r[0]), "=r"(r[1]), "=r"(r[2]), "=r"(r[3]) : "r"(addr));
}
__device__ __forceinline__ void mma_bf16(float* d, const u32* a, const u32 b0, const u32 b1) {
    asm volatile(
        "mma.sync.aligned.m16n8k16.row.col.f32.bf16.bf16.f32 "
        "{%0,%1,%2,%3}, {%4,%5,%6,%7}, {%8,%9}, {%0,%1,%2,%3};"
        : "+f"(d[0]), "+f"(d[1]), "+f"(d[2]), "+f"(d[3])
        : "r"(a[0]), "r"(a[1]), "r"(a[2]), "r"(a[3]), "r"(b0), "r"(b1));
}
__device__ __forceinline__ void mma_f16(float* d, const u32* a, const u32 b0, const u32 b1) {
    asm volatile(
        "mma.sync.aligned.m16n8k16.row.col.f32.f16.f16.f32 "
        "{%0,%1,%2,%3}, {%4,%5,%6,%7}, {%8,%9}, {%0,%1,%2,%3};"
        : "+f"(d[0]), "+f"(d[1]), "+f"(d[2]), "+f"(d[3])
        : "r"(a[0]), "r"(a[1]), "r"(a[2]), "r"(a[3]), "r"(b0), "r"(b1));
}
// f32x2 packed math
__device__ __forceinline__ u64 pk2(float a, float b) {
    u64 r; asm("mov.b64 %0, {%1, %2};" : "=l"(r) : "f"(a), "f"(b)); return r;
}
__device__ __forceinline__ void up2(float& a, float& b, u64 v) {
    asm("mov.b64 {%0, %1}, %2;" : "=f"(a), "=f"(b) : "l"(v));
}
__device__ __forceinline__ u64 mul2(u64 a, u64 b) {
    u64 d; asm("mul.rn.f32x2 %0, %1, %2;" : "=l"(d) : "l"(a), "l"(b)); return d;
}
__device__ __forceinline__ u64 fma2(u64 a, u64 b, u64 c) {
    u64 d; asm("fma.rn.f32x2 %0, %1, %2, %3;" : "=l"(d) : "l"(a), "l"(b), "l"(c)); return d;
}

// ---------------- split HMMA GEMM (128 x 128 tile, fp16) ----------------
// NPROD=2: A hi/lo, B hi.  NPROD=1: A hi, B hi.
#define PITCH 80

template<int NPROD>
__global__ __launch_bounds__(256, 2) void gemm_mma(
    const u16* __restrict__ Ah, const u16* __restrict__ Al,
    const u16* __restrict__ Bh,
    float* __restrict__ C, int N, int K)
{
    constexpr int ABYT = 128 * PITCH;
    constexpr int BBYT = 128 * PITCH;
    constexpr int NA = (NPROD >= 2) ? 2 : 1;
    constexpr int OFF_AL = ABYT;
    constexpr int OFF_BH = NA * ABYT;
    constexpr int STAGE = NA * ABYT + BBYT;

    extern __shared__ __align__(16) char smem[];
    const u32 sb = smem_u32(smem);

    const int tid = threadIdx.x;
    const long brow = (long)blockIdx.y * 128;
    const long bcol = (long)blockIdx.x * 128;

    const int wid  = tid >> 5;
    const int lane = tid & 31;
    const int wm = wid & 1;
    const int wn = wid >> 1;

    const int a_row  = lane & 15;
    const int a_colb = (lane >> 4) * 16;
    const int q = lane >> 3;
    const int b_n  = (lane & 7) + ((q >> 1) << 3);
    const int b_kb = (q & 1) * 16;

    const u32 aAddrH = sb + (u32)((wm*64 + a_row) * PITCH + a_colb);
    const u32 aAddrL = aAddrH + OFF_AL;
    const u32 bAddrH = sb + OFF_BH + (u32)((wn*32 + b_n) * PITCH + b_kb);

    float acc[4][4][4];
    #pragma unroll
    for (int i = 0; i < 4; i++)
        #pragma unroll
        for (int j = 0; j < 4; j++)
            #pragma unroll
            for (int v = 0; v < 4; v++) acc[i][j][v] = 0.0f;

    const int nst = K >> 5;

    auto load_stage = [&](int s) {
        const u32 base = sb + (u32)((s % 3) * STAGE);
        const int kt = s << 5;
        #pragma unroll
        for (int i = tid; i < 512; i += 256) {
            int r = i >> 2, ch = i & 3;
            u32 d = base + (u32)(r * PITCH + ch * 16);
            long g = (brow + r) * (long)K + kt + ch * 8;
            cp16(d, Ah + g);
            if (NPROD >= 2) cp16(d + OFF_AL, Al + g);
        }
        #pragma unroll
        for (int i = tid; i < 512; i += 256) {
            int r = i >> 2, ch = i & 3;
            u32 d = base + OFF_BH + (u32)(r * PITCH + ch * 16);
            long g = (bcol + r) * (long)K + kt + ch * 8;
            cp16(d, Bh + g);
        }
        cp_commit();
    };

    load_stage(0);
    load_stage(1);

    for (int s = 0; s < nst; s++) {
        if (s + 1 < nst) asm volatile("cp.async.wait_group 1;" ::: "memory");
        else             asm volatile("cp.async.wait_group 0;" ::: "memory");
        __syncthreads();
        if (s + 2 < nst) load_stage(s + 2);

        const u32 boff = (u32)((s % 3) * STAGE);
        #pragma unroll
        for (int kk = 0; kk < 2; kk++) {
            const u32 kadd = kk * 32;
            u32 bh[2][4];
            ldsm4(bh[0], bAddrH + boff + kadd);
            ldsm4(bh[1], bAddrH + boff + kadd + 16*PITCH);
            #pragma unroll
            for (int mt = 0; mt < 4; mt++) {
                u32 ah[4], al[4];
                ldsm4(ah, aAddrH + boff + kadd + (u32)(mt*16*PITCH));
                if (NPROD >= 2) ldsm4(al, aAddrL + boff + kadd + (u32)(mt*16*PITCH));
                #pragma unroll
                for (int nt = 0; nt < 4; nt++) {
                    const int p = nt >> 1, h = nt & 1;
                    mma_f16(acc[mt][nt], ah, bh[p][2*h], bh[p][2*h+1]);
                    if (NPROD >= 2) mma_f16(acc[mt][nt], al, bh[p][2*h], bh[p][2*h+1]);
                }
            }
        }
        __syncthreads();
    }

    #pragma unroll
    for (int mt = 0; mt < 4; mt++) {
        long r0 = brow + wm*64 + mt*16 + (lane >> 2);
        long cc = bcol + wn*32 + ((lane & 3) << 1);
        #pragma unroll
        for (int nt = 0; nt < 4; nt++) {
            float2 v0 = make_float2(acc[mt][nt][0], acc[mt][nt][1]);
            float2 v1 = make_float2(acc[mt][nt][2], acc[mt][nt][3]);
            *(float2*)&C[r0 * N + cc + nt*8]     = v0;
            *(float2*)&C[(r0+8) * N + cc + nt*8] = v1;
        }
    }
}

// ---------------- wx GEMM: 64x64 tile, bf16 3-product, 256 threads ----------------
__global__ __launch_bounds__(256, 3) void gemm_wx64(
    const u16* __restrict__ Ah, const u16* __restrict__ Al,
    const u16* __restrict__ Bh, const u16* __restrict__ Bl,
    float* __restrict__ C, int N, int K)
{
    constexpr int ABYT = 64 * PITCH;
    constexpr int OFF_AL = ABYT;
    constexpr int OFF_BH = 2 * ABYT;
    constexpr int OFF_BL = 3 * ABYT;
    constexpr int STAGE = 4 * ABYT;    // 20480

    extern __shared__ __align__(16) char smem[];
    const u32 sb = smem_u32(smem);

    const int tid = threadIdx.x;
    const long brow = (long)blockIdx.y * 64;

    const int wid  = tid >> 5;
    const int lane = tid & 31;
    const int wm = wid & 1;          // 32 rows each
    const int wn = wid >> 1;         // 0..3, 16 cols each

    const int a_row  = lane & 15;
    const int a_colb = (lane >> 4) * 16;
    const int q = lane >> 3;
    const int b_n  = (lane & 7) + ((q >> 1) << 3);
    const int b_kb = (q & 1) * 16;

    const u32 aAddrH = sb + (u32)((wm*32 + a_row) * PITCH + a_colb);
    const u32 aAddrL = aAddrH + OFF_AL;
    const u32 bAddrH = sb + OFF_BH + (u32)((wn*16 + b_n) * PITCH + b_kb);
    const u32 bAddrL = bAddrH + ABYT;

    float acc[2][2][4];
    #pragma unroll
    for (int i = 0; i < 2; i++)
        #pragma unroll
        for (int j = 0; j < 2; j++)
            #pragma unroll
            for (int v = 0; v < 4; v++) acc[i][j][v] = 0.0f;

    const int nst = K >> 5;

    auto load_stage = [&](int s) {
        const u32 base = sb + (u32)((s % 3) * STAGE);
        const int kt = s << 5;
        {
            int i = tid;                      // 256 = 64 rows x 4 chunks
            int r = i >> 2, ch = i & 3;
            u32 d = base + (u32)(r * PITCH + ch * 16);
            long g = (brow + r) * (long)K + kt + ch * 8;
            cp16(d, Ah + g);
            cp16(d + OFF_AL, Al + g);
            long gb = (long)r * K + kt + ch * 8;
            cp16(d + OFF_BH, Bh + gb);
            cp16(d + OFF_BL, Bl + gb);
        }
        cp_commit();
    };

    load_stage(0);
    load_stage(1);

    for (int s = 0; s < nst; s++) {
        if (s + 1 < nst) asm volatile("cp.async.wait_group 1;" ::: "memory");
        else             asm volatile("cp.async.wait_group 0;" ::: "memory");
        __syncthreads();
        if (s + 2 < nst) load_stage(s + 2);

        const u32 boff = (u32)((s % 3) * STAGE);
        #pragma unroll
        for (int kk = 0; kk < 2; kk++) {
            const u32 kadd = kk * 32;
            u32 bh[4], bl[4];
            ldsm4(bh, bAddrH + boff + kadd);
            ldsm4(bl, bAddrL + boff + kadd);
            #pragma unroll
            for (int mt = 0; mt < 2; mt++) {
                u32 ah[4], al[4];
                ldsm4(ah, aAddrH + boff + kadd + (u32)(mt*16*PITCH));
                ldsm4(al, aAddrL + boff + kadd + (u32)(mt*16*PITCH));
                #pragma unroll
                for (int nt = 0; nt < 2; nt++) {
                    mma_bf16(acc[mt][nt], ah, bh[2*nt], bh[2*nt+1]);
                    mma_bf16(acc[mt][nt], ah, bl[2*nt], bl[2*nt+1]);
                    mma_bf16(acc[mt][nt], al, bh[2*nt], bh[2*nt+1]);
                }
            }
        }
        __syncthreads();
    }

    #pragma unroll
    for (int mt = 0; mt < 2; mt++) {
        long r0 = brow + wm*32 + mt*16 + (lane >> 2);
        long cc = wn*16 + ((lane & 3) << 1);
        #pragma unroll
        for (int nt = 0; nt < 2; nt++) {
            float2 v0 = make_float2(acc[mt][nt][0], acc[mt][nt][1]);
            float2 v1 = make_float2(acc[mt][nt][2], acc[mt][nt][3]);
            *(float2*)&C[r0 * N + cc + nt*8]     = v0;
            *(float2*)&C[(r0+8) * N + cc + nt*8] = v1;
        }
    }
}

// ---------------- operand prep kernels ----------------
__global__ __launch_bounds__(256) void split_f16(
    const float* __restrict__ src, __half* __restrict__ hi, __half* __restrict__ lo, int n)
{
    int i = blockIdx.x * 256 + threadIdx.x;
    if (i < n) {
        float v = src[i];
        __half h = __float2half_rn(v);
        hi[i] = h;
        lo[i] = __float2half_rn(v - __half2float(h));
    }
}

__global__ void transpose_f16(
    const float* __restrict__ src, __half* __restrict__ dst, int R, int C)
{
    __shared__ float t[32][33];
    int c0 = blockIdx.x * 32, r0 = blockIdx.y * 32;
    int tx = threadIdx.x, ty = threadIdx.y;
    #pragma unroll
    for (int i = 0; i < 32; i += 8)
        t[ty + i][tx] = src[(long)(r0 + ty + i) * C + c0 + tx];
    __syncthreads();
    #pragma unroll
    for (int i = 0; i < 32; i += 8)
        dst[(long)(c0 + ty + i) * R + r0 + tx] = __float2half_rn(t[tx][ty + i]);
}

__global__ void transpose_split_bf16(
    const float* __restrict__ src, bf16* __restrict__ hi, bf16* __restrict__ lo,
    int R, int C, int Cpad)
{
    __shared__ float t[32][33];
    int c0 = blockIdx.x * 32, r0 = blockIdx.y * 32;
    int tx = threadIdx.x, ty = threadIdx.y;
    #pragma unroll
    for (int i = 0; i < 32; i += 8) {
        int c = c0 + tx;
        float v = (c < C) ? src[(long)(r0 + ty + i) * C + c] : 0.0f;
        t[ty + i][tx] = v;
    }
    __syncthreads();
    #pragma unroll
    for (int i = 0; i < 32; i += 8) {
        int oc = c0 + ty + i;
        if (oc < Cpad) {
            float v = t[tx][ty + i];
            bf16 h = __float2bfloat16_rn(v);
            hi[(long)oc * R + r0 + tx] = h;
            lo[(long)oc * R + r0 + tx] = __float2bfloat16_rn(v - __bfloat162float(h));
        }
    }
}

// ---------------- depthwise causal conv (K=4) + SiLU ----------------
__global__ __launch_bounds__(256) void conv_silu_kernel(
    const float* __restrict__ xz, const float* __restrict__ conv_w,
    const float* __restrict__ conv_b, float* __restrict__ xc,
    bf16* __restrict__ xch, bf16* __restrict__ xcl)
{
    long idx = (long)blockIdx.x * 256 + threadIdx.x;
    int d  = (int)(idx & (DINNER - 1));
    int bl = (int)(idx >> 11);
    int l  = bl & (LL - 1);
    int b  = bl >> 11;
    float acc = conv_b[d];
    #pragma unroll
    for (int k = 0; k < DCONV; k++) {
        int lp = l - (DCONV - 1) + k;
        if (lp >= 0)
            acc += xz[((long)(b * LL + lp)) * (2*DINNER) + d] * conv_w[d * DCONV + k];
    }
    float s = acc / (1.0f + expf(-acc));
    xc[idx] = s;
    bf16 h = __float2bfloat16_rn(s);
    xch[idx] = h;
    xcl[idx] = __float2bfloat16_rn(s - __bfloat162float(h));
}

// ---------------- coef finisher ----------------
__global__ __launch_bounds__(128) void coef_finish(
    const float* __restrict__ xdbl, const float* __restrict__ A_log, float* __restrict__ coef)
{
    int tid = threadIdx.x;
    int rloc = tid >> 4, n = tid & 15;
    long r = (long)blockIdx.x * 8 + rloc;
    const float* xr = xdbl + r * 64;
    float v = xr[0];
    float delta = (v > 20.0f) ? v : log1pf(expf(v));
    float abar = expf(delta * (-expf(A_log[n])));
    float bbar = delta * xr[1 + n];
    float cval = xr[17 + n];
    float* o = coef + r * 48;
    o[n] = abar; o[16 + n] = bbar; o[32 + n] = cval;
}

// ---------------- chunk cumprod: PC[b,l,n] = (prod_{<=l in chunk} a) * C ----------------
__global__ __launch_bounds__(256) void cumprod_kernel(
    const float* __restrict__ coef, float* __restrict__ pc, float* __restrict__ ptot)
{
    __shared__ float sa[CHL*16], sC[CHL*16];
    int c = blockIdx.x, b = blockIdx.y, tid = threadIdx.x;
    long lbase = (long)b * LL + c * CHL;
    for (int i = tid; i < CHL*16; i += 256) {
        int row = i >> 4, n = i & 15;
        sa[i] = coef[(lbase + row)*48 + n];
        sC[i] = coef[(lbase + row)*48 + 32 + n];
    }
    __syncthreads();
    if (tid < 16) {
        float p = 1.0f;
        for (int l = 0; l < CHL; l++) {
            p *= sa[l*16 + tid];
            sa[l*16 + tid] = p * sC[l*16 + tid];
        }
        ptot[(b*NCH + c)*16 + tid] = p;
    }
    __syncthreads();
    for (int i = tid; i < CHL*16; i += 256)
        pc[lbase*16 + i] = sa[i];
}

// ---------------- scan pass 1: local chunk scan, store h_end ----------------
__global__ __launch_bounds__(256) void scan_pass1(
    const float* __restrict__ coef, const float* __restrict__ xc,
    float* __restrict__ hend)
{
    __shared__ float sca[CHL*32];
    int b = blockIdx.z, c = blockIdx.y, tid = threadIdx.x;
    int d = blockIdx.x * 256 + tid;
    long lbase = (long)b * LL + c * CHL;
    for (int i = tid; i < CHL*32; i += 256) {
        int row = i >> 5, j = i & 31;
        sca[i] = coef[(lbase + row)*48 + j];
    }
    __syncthreads();
    u64 h2[8];
    #pragma unroll
    for (int j = 0; j < 8; j++) h2[j] = 0ull;
    for (int l = 0; l < CHL; l++) {
        float xv = xc[(lbase + l)*DINNER + d];
        u64 xx = pk2(xv, xv);
        const u64* ap = (const u64*)&sca[l*32];
        #pragma unroll
        for (int j = 0; j < 8; j++) {
            u64 u = mul2(ap[8+j], xx);
            h2[j] = fma2(ap[j], h2[j], u);
        }
    }
    float* o = hend + (((long)(b*NCH + c) * DINNER) + d) * 16;
    #pragma unroll
    for (int j = 0; j < 8; j++) {
        float x0, x1; up2(x0, x1, h2[j]);
        o[2*j] = x0; o[2*j+1] = x1;
    }
}

// ---------------- scan pass 2: combine chunk carries ----------------
__global__ __launch_bounds__(256) void scan_pass2(
    const float* __restrict__ hend, const float* __restrict__ ptot,
    float* __restrict__ hstart)
{
    long idx = (long)blockIdx.x * 256 + threadIdx.x;   // b*2048*16 + d*16 + n
    int n = (int)(idx & 15);
    int d = (int)((idx >> 4) & (DINNER-1));
    int b = (int)(idx >> 15);
    float hs = 0.0f;
    for (int c = 0; c < NCH; c++) {
        long o = (((long)(b*NCH + c) * DINNER) + d) * 16 + n;
        hstart[o] = hs;
        hs = ptot[(b*NCH + c)*16 + n] * hs + hend[o];
    }
}

// ---------------- scan pass 3: recompute + correction + skip + gate -> fp16 ----------------
__global__ __launch_bounds__(256) void scan_pass3(
    const float* __restrict__ coef, const float* __restrict__ pc,
    const float* __restrict__ hstart, const float* __restrict__ xc,
    const float* __restrict__ xz, const float* __restrict__ Dp,
    __half* __restrict__ yh)
{
    __shared__ float sc[CHL*48];
    __shared__ float spc[CHL*16];
    int b = blockIdx.z, c = blockIdx.y, tid = threadIdx.x;
    int d = blockIdx.x * 256 + tid;
    long lbase = (long)b * LL + c * CHL;
    for (int i = tid; i < CHL*48; i += 256)
        sc[i] = coef[lbase*48 + i];
    for (int i = tid; i < CHL*16; i += 256)
        spc[i] = pc[lbase*16 + i];
    __syncthreads();

    u64 h2[8], hs2[8];
    const u64* hsp = (const u64*)(hstart + (((long)(b*NCH + c) * DINNER) + d) * 16);
    #pragma unroll
    for (int j = 0; j < 8; j++) { h2[j] = 0ull; hs2[j] = hsp[j]; }
    float Dd = Dp[d];

    for (int l = 0; l < CHL; l++) {
        long row = lbase + l;
        float xv = xc[row*DINNER + d];
        float zv = xz[row*(2*DINNER) + DINNER + d];
        u64 xx = pk2(xv, xv);
        const u64* ap = (const u64*)&sc[l*48];   // a:0..7  bb:8..15  C:16..23
        const u64* pp = (const u64*)&spc[l*16];
        u64 y2 = 0ull, r2 = 0ull;
        #pragma unroll
        for (int j = 0; j < 8; j++) {
            u64 u = mul2(ap[8+j], xx);
            h2[j] = fma2(ap[j], h2[j], u);
            y2 = fma2(h2[j], ap[16+j], y2);
            r2 = fma2(pp[j], hs2[j], r2);
        }
        float y0, y1, r0, r1;
        up2(y0, y1, y2); up2(r0, r1, r2);
        float y = y0 + y1 + r0 + r1 + xv * Dd;
        float sg = zv / (1.0f + expf(-zv));
        yh[row*DINNER + d] = __float2half_rn(y * sg);
    }
}

// ---------------- launch ----------------
extern "C" void kernel_launch(void* const* d_in, const int* in_sizes, int n_in,
                              void* d_out, int out_size)
{
    const float* x       = (const float*)d_in[0];
    const float* W_in    = (const float*)d_in[1];
    const float* conv_w  = (const float*)d_in[2];
    const float* conv_b  = (const float*)d_in[3];
    const float* W_x     = (const float*)d_in[4];
    const float* A_log   = (const float*)d_in[5];
    const float* D_param = (const float*)d_in[6];
    const float* W_out   = (const float*)d_in[7];
    float* out = (float*)d_out;

    float *xz, *xc, *coefp, *xdbl, *pc, *ptot, *hend, *hstart;
    __half *xh, *xl, *winT, *woutT, *yh;
    bf16 *xch, *xcl, *wxh, *wxl;
    cudaGetSymbolAddress((void**)&xz,    g_xz);
    cudaGetSymbolAddress((void**)&xc,    g_xc);
    cudaGetSymbolAddress((void**)&coefp, g_coef);
    cudaGetSymbolAddress((void**)&xdbl,  g_xdbl);
    cudaGetSymbolAddress((void**)&pc,    g_pc);
    cudaGetSymbolAddress((void**)&ptot,  g_ptot);
    cudaGetSymbolAddress((void**)&hend,  g_hend);
    cudaGetSymbolAddress((void**)&hstart,g_hstart);
    cudaGetSymbolAddress((void**)&xh,    g_xh);
    cudaGetSymbolAddress((void**)&xl,    g_xl);
    cudaGetSymbolAddress((void**)&winT,  g_winT);
    cudaGetSymbolAddress((void**)&woutT, g_woutT);
    cudaGetSymbolAddress((void**)&xch,   g_xch);
    cudaGetSymbolAddress((void**)&xcl,   g_xcl);
    cudaGetSymbolAddress((void**)&wxh,   g_wxT_h);
    cudaGetSymbolAddress((void**)&wxl,   g_wxT_l);
    cudaGetSymbolAddress((void**)&yh,    g_yh);

    const int SMEM2 = 3 * (2*128*80 + 128*80);   // 92160
    const int SMEM1 = 3 * (128*80 + 128*80);     // 61440
    const int SMEMW = 3 * (4*64*80);             // 61440
    cudaFuncSetAttribute((const void*)gemm_mma<2>, cudaFuncAttributeMaxDynamicSharedMemorySize, SMEM2);
    cudaFuncSetAttribute((const void*)gemm_mma<1>, cudaFuncAttributeMaxDynamicSharedMemorySize, SMEM1);
    cudaFuncSetAttribute((const void*)gemm_wx64,   cudaFuncAttributeMaxDynamicSharedMemorySize, SMEMW);

    // 1) operand prep
    split_f16<<<(M_ROWS*DMODEL)/256, 256>>>(x, xh, xl, M_ROWS*DMODEL);
    transpose_f16<<<dim3(4096/32, 1024/32), dim3(32,8)>>>(W_in,  winT,  1024, 4096);
    transpose_f16<<<dim3(1024/32, 2048/32), dim3(32,8)>>>(W_out, woutT, 2048, 1024);
    transpose_split_bf16<<<dim3(64/32, 2048/32), dim3(32,8)>>>(W_x, wxh, wxl, 2048, 33, 64);

    // 2) xz = x @ W_in  (fp16 2-product)
    gemm_mma<2><<<dim3(4096/128, 8192/128), 256, SMEM2>>>(
        (const u16*)xh, (const u16*)xl, (const u16*)winT, xz, 4096, 1024);

    // 3) conv + silu
    conv_silu_kernel<<<(M_ROWS*DINNER)/256, 256>>>(xz, conv_w, conv_b, xc, xch, xcl);

    // 4) x_dbl = xc @ W_x  (bf16 3-product, 64x64 tiles)
    gemm_wx64<<<dim3(1, 8192/64), 256, SMEMW>>>(
        (const u16*)xch, (const u16*)xcl, (const u16*)wxh, (const u16*)wxl, xdbl, 64, 2048);

    // 5) coefficients + chunk cumprods
    coef_finish<<<M_ROWS/8, 128>>>(xdbl, A_log, coefp);
    cumprod_kernel<<<dim3(NCH, BB), 256>>>(coefp, pc, ptot);

    // 6) chunked parallel scan
    scan_pass1<<<dim3(DINNER/256, NCH, BB), 256>>>(coefp, xc, hend);
    scan_pass2<<<(BB*DINNER*DSTATE)/256, 256>>>(hend, ptot, hstart);
    scan_pass3<<<dim3(DINNER/256, NCH, BB), 256>>>(coefp, pc, hstart, xc, xz, D_param, yh);

    // 7) out = y @ W_out  (fp16 1-product)
    gemm_mma<1><<<dim3(1024/128, 8192/128), 256, SMEM1>>>(
        (const u16*)yh, nullptr, (const u16*)woutT, out, 1024, 2048);
}

// round 6
// speedup vs baseline: 4.4185x; 1.2235x over previous
#include <cuda_runtime.h>
#include <cuda_bf16.h>
#include <cuda_fp16.h>
#include <math.h>
#include <stdint.h>

#define BB 4
#define LL 2048
#define DMODEL 1024
#define DSTATE 16
#define DCONV 4
#define DINNER 2048
#define M_ROWS (BB*LL)            // 8192
#define NCH 16                    // chunks per sequence
#define CHL 128                   // chunk length

typedef unsigned int u32;
typedef unsigned long long u64;
typedef __nv_bfloat16 bf16;
typedef uint16_t u16;

// ---------------- scratch (device globals) ----------------
__device__ __align__(16) float g_xz[(size_t)M_ROWS * (2*DINNER)];
__device__ __align__(16) __half g_xh[(size_t)M_ROWS * DMODEL];
__device__ __align__(16) __half g_winT[(size_t)(2*DINNER) * DMODEL];
__device__ __align__(16) float g_xc[(size_t)M_ROWS * DINNER];
__device__ __align__(16) bf16  g_xch[(size_t)M_ROWS * DINNER];
__device__ __align__(16) bf16  g_xcl[(size_t)M_ROWS * DINNER];
__device__ __align__(16) bf16  g_wxT_h[64 * DINNER];
__device__ __align__(16) bf16  g_wxT_l[64 * DINNER];
__device__ __align__(16) float g_xdbl[(size_t)M_ROWS * 64];
__device__ __align__(16) float g_coef[(size_t)M_ROWS * 48];
__device__ __align__(16) float g_pc[(size_t)M_ROWS * DSTATE];
__device__ __align__(16) float g_ptot[BB * NCH * DSTATE];
__device__ __align__(16) float g_hend[(size_t)BB * NCH * DINNER * DSTATE];
__device__ __align__(16) float g_hstart[(size_t)BB * NCH * DINNER * DSTATE];
__device__ __align__(16) __half g_yh[(size_t)M_ROWS * DINNER];
__device__ __align__(16) __half g_woutT[(size_t)DMODEL * DINNER];

// ---------------- PTX helpers (BASE PTX ONLY) ----------------
__device__ __forceinline__ u32 smem_u32(const void* p) {
    u32 a; asm("{ .reg .u64 t; cvta.to.shared.u64 t, %1; cvt.u32.u64 %0, t; }" : "=r"(a) : "l"(p));
    return a;
}
__device__ __forceinline__ void cp16(u32 dst, const void* src) {
    asm volatile("cp.async.cg.shared.global [%0], [%1], 16;" :: "r"(dst), "l"(src));
}
__device__ __forceinline__ void cp_commit() {
    asm volatile("cp.async.commit_group;" ::: "memory");
}
__device__ __forceinline__ void ldsm4(u32* r, u32 addr) {
    asm volatile("ldmatrix.sync.aligned.m8n8.x4.shared.b16 {%0,%1,%2,%3}, [%4];"
                 : "=r"(r[0]), "=r"(r[1]), "=r"(r[2]), "=r"(r[3]) : "r"(addr));
}
__device__ __forceinline__ void mma_bf16(float* d, const u32* a, const u32 b0, const u32 b1) {
    asm volatile(
        "mma.sync.aligned.m16n8k16.row.col.f32.bf16.bf16.f32 "
        "{%0,%1,%2,%3}, {%4,%5,%6,%7}, {%8,%9}, {%0,%1,%2,%3};"
        : "+f"(d[0]), "+f"(d[1]), "+f"(d[2]), "+f"(d[3])
        : "r"(a[0]), "r"(a[1]), "r"(a[2]), "r"(a[3]), "r"(b0), "r"(b1));
}
__device__ __forceinline__ void mma_f16(float* d, const u32* a, const u32 b0, const u32 b1) {
    asm volatile(
        "mma.sync.aligned.m16n8k16.row.col.f32.f16.f16.f32 "
        "{%0,%1,%2,%3}, {%4,%5,%6,%7}, {%8,%9}, {%0,%1,%2,%3};"
        : "+f"(d[0]), "+f"(d[1]), "+f"(d[2]), "+f"(d[3])
        : "r"(a[0]), "r"(a[1]), "r"(a[2]), "r"(a[3]), "r"(b0), "r"(b1));
}
__device__ __forceinline__ u64 pk2(float a, float b) {
    u64 r; asm("mov.b64 %0, {%1, %2};" : "=l"(r) : "f"(a), "f"(b)); return r;
}
__device__ __forceinline__ void up2(float& a, float& b, u64 v) {
    asm("mov.b64 {%0, %1}, %2;" : "=f"(a), "=f"(b) : "l"(v));
}
__device__ __forceinline__ u64 mul2(u64 a, u64 b) {
    u64 d; asm("mul.rn.f32x2 %0, %1, %2;" : "=l"(d) : "l"(a), "l"(b)); return d;
}
__device__ __forceinline__ u64 fma2(u64 a, u64 b, u64 c) {
    u64 d; asm("fma.rn.f32x2 %0, %1, %2, %3;" : "=l"(d) : "l"(a), "l"(b), "l"(c)); return d;
}

// ---------------- fp16 1-product HMMA GEMM, 128x128 tile, 4-stage ring ----------------
#define PITCH 80

__global__ __launch_bounds__(256, 2) void gemm_f16(
    const u16* __restrict__ Ah, const u16* __restrict__ Bh,
    float* __restrict__ C, int N, int K)
{
    constexpr int ABYT = 128 * PITCH;
    constexpr int STAGE = 2 * ABYT;       // 20480

    extern __shared__ __align__(16) char smem[];
    const u32 sb = smem_u32(smem);

    const int tid = threadIdx.x;
    const long brow = (long)blockIdx.y * 128;
    const long bcol = (long)blockIdx.x * 128;

    const int wid  = tid >> 5;
    const int lane = tid & 31;
    const int wm = wid & 1;
    const int wn = wid >> 1;

    const int a_row  = lane & 15;
    const int a_colb = (lane >> 4) * 16;
    const int q = lane >> 3;
    const int b_n  = (lane & 7) + ((q >> 1) << 3);
    const int b_kb = (q & 1) * 16;

    const u32 aAddr = sb + (u32)((wm*64 + a_row) * PITCH + a_colb);
    const u32 bAddr = sb + ABYT + (u32)((wn*32 + b_n) * PITCH + b_kb);

    float acc[4][4][4];
    #pragma unroll
    for (int i = 0; i < 4; i++)
        #pragma unroll
        for (int j = 0; j < 4; j++)
            #pragma unroll
            for (int v = 0; v < 4; v++) acc[i][j][v] = 0.0f;

    const int nst = K >> 5;

    auto load_stage = [&](int s) {
        const u32 base = sb + (u32)((s & 3) * STAGE);
        const int kt = s << 5;
        #pragma unroll
        for (int i = tid; i < 512; i += 256) {
            int r = i >> 2, ch = i & 3;
            u32 d = base + (u32)(r * PITCH + ch * 16);
            cp16(d, Ah + (brow + r) * (long)K + kt + ch * 8);
            cp16(d + ABYT, Bh + (bcol + r) * (long)K + kt + ch * 8);
        }
        cp_commit();
    };

    load_stage(0);
    load_stage(1);
    load_stage(2);

    for (int s = 0; s < nst; s++) {
        const int rem = nst - 1 - s;
        if (rem >= 2)      asm volatile("cp.async.wait_group 2;" ::: "memory");
        else if (rem == 1) asm volatile("cp.async.wait_group 1;" ::: "memory");
        else               asm volatile("cp.async.wait_group 0;" ::: "memory");
        __syncthreads();
        if (s + 3 < nst) load_stage(s + 3);   // writes buf (s+3)&3 = (s-1)&3, freed by sync

        const u32 boff = (u32)((s & 3) * STAGE);
        #pragma unroll
        for (int kk = 0; kk < 2; kk++) {
            const u32 kadd = kk * 32;
            u32 bh[2][4];
            ldsm4(bh[0], bAddr + boff + kadd);
            ldsm4(bh[1], bAddr + boff + kadd + 16*PITCH);
            #pragma unroll
            for (int mt = 0; mt < 4; mt++) {
                u32 ah[4];
                ldsm4(ah, aAddr + boff + kadd + (u32)(mt*16*PITCH));
                #pragma unroll
                for (int nt = 0; nt < 4; nt++) {
                    const int p = nt >> 1, h = nt & 1;
                    mma_f16(acc[mt][nt], ah, bh[p][2*h], bh[p][2*h+1]);
                }
            }
        }
        __syncthreads();
    }

    #pragma unroll
    for (int mt = 0; mt < 4; mt++) {
        long r0 = brow + wm*64 + mt*16 + (lane >> 2);
        long cc = bcol + wn*32 + ((lane & 3) << 1);
        #pragma unroll
        for (int nt = 0; nt < 4; nt++) {
            float2 v0 = make_float2(acc[mt][nt][0], acc[mt][nt][1]);
            float2 v1 = make_float2(acc[mt][nt][2], acc[mt][nt][3]);
            *(float2*)&C[r0 * N + cc + nt*8]     = v0;
            *(float2*)&C[(r0+8) * N + cc + nt*8] = v1;
        }
    }
}

// ---------------- wx GEMM: 64x64 tile, bf16 3-product, 256 threads ----------------
__global__ __launch_bounds__(256, 3) void gemm_wx64(
    const u16* __restrict__ Ah, const u16* __restrict__ Al,
    const u16* __restrict__ Bh, const u16* __restrict__ Bl,
    float* __restrict__ C, int N, int K)
{
    constexpr int ABYT = 64 * PITCH;
    constexpr int OFF_AL = ABYT;
    constexpr int OFF_BH = 2 * ABYT;
    constexpr int OFF_BL = 3 * ABYT;
    constexpr int STAGE = 4 * ABYT;

    extern __shared__ __align__(16) char smem[];
    const u32 sb = smem_u32(smem);

    const int tid = threadIdx.x;
    const long brow = (long)blockIdx.y * 64;

    const int wid  = tid >> 5;
    const int lane = tid & 31;
    const int wm = wid & 1;
    const int wn = wid >> 1;

    const int a_row  = lane & 15;
    const int a_colb = (lane >> 4) * 16;
    const int q = lane >> 3;
    const int b_n  = (lane & 7) + ((q >> 1) << 3);
    const int b_kb = (q & 1) * 16;

    const u32 aAddrH = sb + (u32)((wm*32 + a_row) * PITCH + a_colb);
    const u32 aAddrL = aAddrH + OFF_AL;
    const u32 bAddrH = sb + OFF_BH + (u32)((wn*16 + b_n) * PITCH + b_kb);
    const u32 bAddrL = bAddrH + ABYT;

    float acc[2][2][4];
    #pragma unroll
    for (int i = 0; i < 2; i++)
        #pragma unroll
        for (int j = 0; j < 2; j++)
            #pragma unroll
            for (int v = 0; v < 4; v++) acc[i][j][v] = 0.0f;

    const int nst = K >> 5;

    auto load_stage = [&](int s) {
        const u32 base = sb + (u32)((s % 3) * STAGE);
        const int kt = s << 5;
        {
            int i = tid;
            int r = i >> 2, ch = i & 3;
            u32 d = base + (u32)(r * PITCH + ch * 16);
            long g = (brow + r) * (long)K + kt + ch * 8;
            cp16(d, Ah + g);
            cp16(d + OFF_AL, Al + g);
            long gb = (long)r * K + kt + ch * 8;
            cp16(d + OFF_BH, Bh + gb);
            cp16(d + OFF_BL, Bl + gb);
        }
        cp_commit();
    };

    load_stage(0);
    load_stage(1);

    for (int s = 0; s < nst; s++) {
        if (s + 1 < nst) asm volatile("cp.async.wait_group 1;" ::: "memory");
        else             asm volatile("cp.async.wait_group 0;" ::: "memory");
        __syncthreads();
        if (s + 2 < nst) load_stage(s + 2);

        const u32 boff = (u32)((s % 3) * STAGE);
        #pragma unroll
        for (int kk = 0; kk < 2; kk++) {
            const u32 kadd = kk * 32;
            u32 bh[4], bl[4];
            ldsm4(bh, bAddrH + boff + kadd);
            ldsm4(bl, bAddrL + boff + kadd);
            #pragma unroll
            for (int mt = 0; mt < 2; mt++) {
                u32 ah[4], al[4];
                ldsm4(ah, aAddrH + boff + kadd + (u32)(mt*16*PITCH));
                ldsm4(al, aAddrL + boff + kadd + (u32)(mt*16*PITCH));
                #pragma unroll
                for (int nt = 0; nt < 2; nt++) {
                    mma_bf16(acc[mt][nt], ah, bh[2*nt], bh[2*nt+1]);
                    mma_bf16(acc[mt][nt], ah, bl[2*nt], bl[2*nt+1]);
                    mma_bf16(acc[mt][nt], al, bh[2*nt], bh[2*nt+1]);
                }
            }
        }
        __syncthreads();
    }

    #pragma unroll
    for (int mt = 0; mt < 2; mt++) {
        long r0 = brow + wm*32 + mt*16 + (lane >> 2);
        long cc = wn*16 + ((lane & 3) << 1);
        #pragma unroll
        for (int nt = 0; nt < 2; nt++) {
            float2 v0 = make_float2(acc[mt][nt][0], acc[mt][nt][1]);
            float2 v1 = make_float2(acc[mt][nt][2], acc[mt][nt][3]);
            *(float2*)&C[r0 * N + cc + nt*8]     = v0;
            *(float2*)&C[(r0+8) * N + cc + nt*8] = v1;
        }
    }
}

// ---------------- operand prep kernels ----------------
__global__ __launch_bounds__(256) void convert_f16(
    const float* __restrict__ src, __half* __restrict__ dst, int n)
{
    int i = blockIdx.x * 256 + threadIdx.x;
    if (i < n) dst[i] = __float2half_rn(src[i]);
}

__global__ void transpose_f16(
    const float* __restrict__ src, __half* __restrict__ dst, int R, int C)
{
    __shared__ float t[32][33];
    int c0 = blockIdx.x * 32, r0 = blockIdx.y * 32;
    int tx = threadIdx.x, ty = threadIdx.y;
    #pragma unroll
    for (int i = 0; i < 32; i += 8)
        t[ty + i][tx] = src[(long)(r0 + ty + i) * C + c0 + tx];
    __syncthreads();
    #pragma unroll
    for (int i = 0; i < 32; i += 8)
        dst[(long)(c0 + ty + i) * R + r0 + tx] = __float2half_rn(t[tx][ty + i]);
}

__global__ void transpose_split_bf16(
    const float* __restrict__ src, bf16* __restrict__ hi, bf16* __restrict__ lo,
    int R, int C, int Cpad)
{
    __shared__ float t[32][33];
    int c0 = blockIdx.x * 32, r0 = blockIdx.y * 32;
    int tx = threadIdx.x, ty = threadIdx.y;
    #pragma unroll
    for (int i = 0; i < 32; i += 8) {
        int c = c0 + tx;
        float v = (c < C) ? src[(long)(r0 + ty + i) * C + c] : 0.0f;
        t[ty + i][tx] = v;
    }
    __syncthreads();
    #pragma unroll
    for (int i = 0; i < 32; i += 8) {
        int oc = c0 + ty + i;
        if (oc < Cpad) {
            float v = t[tx][ty + i];
            bf16 h = __float2bfloat16_rn(v);
            hi[(long)oc * R + r0 + tx] = h;
            lo[(long)oc * R + r0 + tx] = __float2bfloat16_rn(v - __bfloat162float(h));
        }
    }
}

// ---------------- depthwise causal conv (K=4) + SiLU ----------------
__global__ __launch_bounds__(256) void conv_silu_kernel(
    const float* __restrict__ xz, const float* __restrict__ conv_w,
    const float* __restrict__ conv_b, float* __restrict__ xc,
    bf16* __restrict__ xch, bf16* __restrict__ xcl)
{
    long idx = (long)blockIdx.x * 256 + threadIdx.x;
    int d  = (int)(idx & (DINNER - 1));
    int bl = (int)(idx >> 11);
    int l  = bl & (LL - 1);
    int b  = bl >> 11;
    float acc = conv_b[d];
    #pragma unroll
    for (int k = 0; k < DCONV; k++) {
        int lp = l - (DCONV - 1) + k;
        if (lp >= 0)
            acc += xz[((long)(b * LL + lp)) * (2*DINNER) + d] * conv_w[d * DCONV + k];
    }
    float s = acc / (1.0f + expf(-acc));
    xc[idx] = s;
    bf16 h = __float2bfloat16_rn(s);
    xch[idx] = h;
    xcl[idx] = __float2bfloat16_rn(s - __bfloat162float(h));
}

// ---------------- coef finisher ----------------
__global__ __launch_bounds__(128) void coef_finish(
    const float* __restrict__ xdbl, const float* __restrict__ A_log, float* __restrict__ coef)
{
    int tid = threadIdx.x;
    int rloc = tid >> 4, n = tid & 15;
    long r = (long)blockIdx.x * 8 + rloc;
    const float* xr = xdbl + r * 64;
    float v = xr[0];
    float delta = (v > 20.0f) ? v : log1pf(expf(v));
    float abar = expf(delta * (-expf(A_log[n])));
    float bbar = delta * xr[1 + n];
    float cval = xr[17 + n];
    float* o = coef + r * 48;
    o[n] = abar; o[16 + n] = bbar; o[32 + n] = cval;
}

// ---------------- chunk cumprod ----------------
__global__ __launch_bounds__(256) void cumprod_kernel(
    const float* __restrict__ coef, float* __restrict__ pc, float* __restrict__ ptot)
{
    __shared__ float sa[CHL*16], sC[CHL*16];
    int c = blockIdx.x, b = blockIdx.y, tid = threadIdx.x;
    long lbase = (long)b * LL + c * CHL;
    for (int i = tid; i < CHL*16; i += 256) {
        int row = i >> 4, n = i & 15;
        sa[i] = coef[(lbase + row)*48 + n];
        sC[i] = coef[(lbase + row)*48 + 32 + n];
    }
    __syncthreads();
    if (tid < 16) {
        float p = 1.0f;
        for (int l = 0; l < CHL; l++) {
            p *= sa[l*16 + tid];
            sa[l*16 + tid] = p * sC[l*16 + tid];
        }
        ptot[(b*NCH + c)*16 + tid] = p;
    }
    __syncthreads();
    for (int i = tid; i < CHL*16; i += 256)
        pc[lbase*16 + i] = sa[i];
}

// ---------------- scan pass 1 ----------------
__global__ __launch_bounds__(256) void scan_pass1(
    const float* __restrict__ coef, const float* __restrict__ xc,
    float* __restrict__ hend)
{
    __shared__ float sca[CHL*32];
    int b = blockIdx.z, c = blockIdx.y, tid = threadIdx.x;
    int d = blockIdx.x * 256 + tid;
    long lbase = (long)b * LL + c * CHL;
    for (int i = tid; i < CHL*32; i += 256) {
        int row = i >> 5, j = i & 31;
        sca[i] = coef[(lbase + row)*48 + j];
    }
    __syncthreads();
    u64 h2[8];
    #pragma unroll
    for (int j = 0; j < 8; j++) h2[j] = 0ull;
    for (int l = 0; l < CHL; l++) {
        float xv = xc[(lbase + l)*DINNER + d];
        u64 xx = pk2(xv, xv);
        const u64* ap = (const u64*)&sca[l*32];
        #pragma unroll
        for (int j = 0; j < 8; j++) {
            u64 u = mul2(ap[8+j], xx);
            h2[j] = fma2(ap[j], h2[j], u);
        }
    }
    float* o = hend + (((long)(b*NCH + c) * DINNER) + d) * 16;
    #pragma unroll
    for (int j = 0; j < 8; j++) {
        float x0, x1; up2(x0, x1, h2[j]);
        o[2*j] = x0; o[2*j+1] = x1;
    }
}

// ---------------- scan pass 2 ----------------
__global__ __launch_bounds__(256) void scan_pass2(
    const float* __restrict__ hend, const float* __restrict__ ptot,
    float* __restrict__ hstart)
{
    long idx = (long)blockIdx.x * 256 + threadIdx.x;
    int n = (int)(idx & 15);
    int d = (int)((idx >> 4) & (DINNER-1));
    int b = (int)(idx >> 15);
    float hs = 0.0f;
    for (int c = 0; c < NCH; c++) {
        long o = (((long)(b*NCH + c) * DINNER) + d) * 16 + n;
        hstart[o] = hs;
        hs = ptot[(b*NCH + c)*16 + n] * hs + hend[o];
    }
}

// ---------------- scan pass 3 ----------------
__global__ __launch_bounds__(256) void scan_pass3(
    const float* __restrict__ coef, const float* __restrict__ pc,
    const float* __restrict__ hstart, const float* __restrict__ xc,
    const float* __restrict__ xz, const float* __restrict__ Dp,
    __half* __restrict__ yh)
{
    __shared__ float sc[CHL*48];
    __shared__ float spc[CHL*16];
    int b = blockIdx.z, c = blockIdx.y, tid = threadIdx.x;
    int d = blockIdx.x * 256 + tid;
    long lbase = (long)b * LL + c * CHL;
    for (int i = tid; i < CHL*48; i += 256)
        sc[i] = coef[lbase*48 + i];
    for (int i = tid; i < CHL*16; i += 256)
        spc[i] = pc[lbase*16 + i];
    __syncthreads();

    u64 h2[8], hs2[8];
    const u64* hsp = (const u64*)(hstart + (((long)(b*NCH + c) * DINNER) + d) * 16);
    #pragma unroll
    for (int j = 0; j < 8; j++) { h2[j] = 0ull; hs2[j] = hsp[j]; }
    float Dd = Dp[d];

    for (int l = 0; l < CHL; l++) {
        long row = lbase + l;
        float xv = xc[row*DINNER + d];
        float zv = xz[row*(2*DINNER) + DINNER + d];
        u64 xx = pk2(xv, xv);
        const u64* ap = (const u64*)&sc[l*48];
        const u64* pp = (const u64*)&spc[l*16];
        u64 y2 = 0ull, r2 = 0ull;
        #pragma unroll
        for (int j = 0; j < 8; j++) {
            u64 u = mul2(ap[8+j], xx);
            h2[j] = fma2(ap[j], h2[j], u);
            y2 = fma2(h2[j], ap[16+j], y2);
            r2 = fma2(pp[j], hs2[j], r2);
        }
        float y0, y1, r0, r1;
        up2(y0, y1, y2); up2(r0, r1, r2);
        float y = y0 + y1 + r0 + r1 + xv * Dd;
        float sg = zv / (1.0f + expf(-zv));
        yh[row*DINNER + d] = __float2half_rn(y * sg);
    }
}

// ---------------- launch ----------------
extern "C" void kernel_launch(void* const* d_in, const int* in_sizes, int n_in,
                              void* d_out, int out_size)
{
    const float* x       = (const float*)d_in[0];
    const float* W_in    = (const float*)d_in[1];
    const float* conv_w  = (const float*)d_in[2];
    const float* conv_b  = (const float*)d_in[3];
    const float* W_x     = (const float*)d_in[4];
    const float* A_log   = (const float*)d_in[5];
    const float* D_param = (const float*)d_in[6];
    const float* W_out   = (const float*)d_in[7];
    float* out = (float*)d_out;

    float *xz, *xc, *coefp, *xdbl, *pc, *ptot, *hend, *hstart;
    __half *xh, *winT, *woutT, *yh;
    bf16 *xch, *xcl, *wxh, *wxl;
    cudaGetSymbolAddress((void**)&xz,    g_xz);
    cudaGetSymbolAddress((void**)&xc,    g_xc);
    cudaGetSymbolAddress((void**)&coefp, g_coef);
    cudaGetSymbolAddress((void**)&xdbl,  g_xdbl);
    cudaGetSymbolAddress((void**)&pc,    g_pc);
    cudaGetSymbolAddress((void**)&ptot,  g_ptot);
    cudaGetSymbolAddress((void**)&hend,  g_hend);
    cudaGetSymbolAddress((void**)&hstart,g_hstart);
    cudaGetSymbolAddress((void**)&xh,    g_xh);
    cudaGetSymbolAddress((void**)&winT,  g_winT);
    cudaGetSymbolAddress((void**)&woutT, g_woutT);
    cudaGetSymbolAddress((void**)&xch,   g_xch);
    cudaGetSymbolAddress((void**)&xcl,   g_xcl);
    cudaGetSymbolAddress((void**)&wxh,   g_wxT_h);
    cudaGetSymbolAddress((void**)&wxl,   g_wxT_l);
    cudaGetSymbolAddress((void**)&yh,    g_yh);

    const int SMEM1 = 4 * (2*128*80);            // 81920, 4-stage
    const int SMEMW = 3 * (4*64*80);             // 61440
    cudaFuncSetAttribute((const void*)gemm_f16,  cudaFuncAttributeMaxDynamicSharedMemorySize, SMEM1);
    cudaFuncSetAttribute((const void*)gemm_wx64, cudaFuncAttributeMaxDynamicSharedMemorySize, SMEMW);

    // 1) operand prep
    convert_f16<<<(M_ROWS*DMODEL)/256, 256>>>(x, xh, M_ROWS*DMODEL);
    transpose_f16<<<dim3(4096/32, 1024/32), dim3(32,8)>>>(W_in,  winT,  1024, 4096);
    transpose_f16<<<dim3(1024/32, 2048/32), dim3(32,8)>>>(W_out, woutT, 2048, 1024);
    transpose_split_bf16<<<dim3(64/32, 2048/32), dim3(32,8)>>>(W_x, wxh, wxl, 2048, 33, 64);

    // 2) xz = x @ W_in  (fp16 1-product)
    gemm_f16<<<dim3(4096/128, 8192/128), 256, SMEM1>>>(
        (const u16*)xh, (const u16*)winT, xz, 4096, 1024);

    // 3) conv + silu
    conv_silu_kernel<<<(M_ROWS*DINNER)/256, 256>>>(xz, conv_w, conv_b, xc, xch, xcl);

    // 4) x_dbl = xc @ W_x  (bf16 3-product)
    gemm_wx64<<<dim3(1, 8192/64), 256, SMEMW>>>(
        (const u16*)xch, (const u16*)xcl, (const u16*)wxh, (const u16*)wxl, xdbl, 64, 2048);

    // 5) coefficients + chunk cumprods
    coef_finish<<<M_ROWS/8, 128>>>(xdbl, A_log, coefp);
    cumprod_kernel<<<dim3(NCH, BB), 256>>>(coefp, pc, ptot);

    // 6) chunked parallel scan
    scan_pass1<<<dim3(DINNER/256, NCH, BB), 256>>>(coefp, xc, hend);
    scan_pass2<<<(BB*DINNER*DSTATE)/256, 256>>>(hend, ptot, hstart);
    scan_pass3<<<dim3(DINNER/256, NCH, BB), 256>>>(coefp, pc, hstart, xc, xz, D_param, yh);

    // 7) out = y @ W_out  (fp16 1-product)
    gemm_f16<<<dim3(1024/128, 8192/128), 256, SMEM1>>>(
        (const u16*)yh, (const u16*)woutT, out, 1024, 2048);
}

// round 7
// speedup vs baseline: 5.2343x; 1.1846x over previous
#include <cuda_runtime.h>
#include <cuda_bf16.h>
#include <cuda_fp16.h>
#include <math.h>
#include <stdint.h>

#define BB 4
#define LL 2048
#define DMODEL 1024
#define DSTATE 16
#define DCONV 4
#define DINNER 2048
#define M_ROWS (BB*LL)            // 8192
#define NCH 16                    // chunks per sequence
#define CHL 128                   // chunk length

typedef unsigned int u32;
typedef unsigned long long u64;
typedef __nv_bfloat16 bf16;
typedef uint16_t u16;

// ---------------- scratch (device globals) ----------------
__device__ __align__(16) float g_xz[(size_t)M_ROWS * (2*DINNER)];
__device__ __align__(16) __half g_xh[(size_t)M_ROWS * DMODEL];
__device__ __align__(16) __half g_winT[(size_t)(2*DINNER) * DMODEL];
__device__ __align__(16) float g_xc[(size_t)M_ROWS * DINNER];
__device__ __align__(16) bf16  g_xch[(size_t)M_ROWS * DINNER];
__device__ __align__(16) bf16  g_xcl[(size_t)M_ROWS * DINNER];
__device__ __align__(16) bf16  g_wxT_h[64 * DINNER];
__device__ __align__(16) bf16  g_wxT_l[64 * DINNER];
__device__ __align__(16) float g_xdbl[(size_t)M_ROWS * 64];
__device__ __align__(16) float g_coef[(size_t)M_ROWS * 48];
__device__ __align__(16) float g_ptot[BB * NCH * DSTATE];
__device__ __align__(16) float g_hend[(size_t)BB * NCH * DINNER * DSTATE];
__device__ __align__(16) float g_hstart[(size_t)BB * NCH * DINNER * DSTATE];
__device__ __align__(16) __half g_yh[(size_t)M_ROWS * DINNER];
__device__ __align__(16) __half g_woutT[(size_t)DMODEL * DINNER];

// ---------------- PTX helpers (BASE PTX ONLY) ----------------
__device__ __forceinline__ u32 smem_u32(const void* p) {
    u32 a; asm("{ .reg .u64 t; cvta.to.shared.u64 t, %1; cvt.u32.u64 %0, t; }" : "=r"(a) : "l"(p));
    return a;
}
__device__ __forceinline__ void cp16(u32 dst, const void* src) {
    asm volatile("cp.async.cg.shared.global [%0], [%1], 16;" :: "r"(dst), "l"(src));
}
__device__ __forceinline__ void cp_commit() {
    asm volatile("cp.async.commit_group;" ::: "memory");
}
__device__ __forceinline__ void ldsm4(u32* r, u32 addr) {
    asm volatile("ldmatrix.sync.aligned.m8n8.x4.shared.b16 {%0,%1,%2,%3}, [%4];"
                 : "=r"(r[0]), "=r"(r[1]), "=r"(r[2]), "=r"(r[3]) : "r"(addr));
}
__device__ __forceinline__ void mma_bf16(float* d, const u32* a, const u32 b0, const u32 b1) {
    asm volatile(
        "mma.sync.aligned.m16n8k16.row.col.f32.bf16.bf16.f32 "
        "{%0,%1,%2,%3}, {%4,%5,%6,%7}, {%8,%9}, {%0,%1,%2,%3};"
        : "+f"(d[0]), "+f"(d[1]), "+f"(d[2]), "+f"(d[3])
        : "r"(a[0]), "r"(a[1]), "r"(a[2]), "r"(a[3]), "r"(b0), "r"(b1));
}
__device__ __forceinline__ void mma_f16(float* d, const u32* a, const u32 b0, const u32 b1) {
    asm volatile(
        "mma.sync.aligned.m16n8k16.row.col.f32.f16.f16.f32 "
        "{%0,%1,%2,%3}, {%4,%5,%6,%7}, {%8,%9}, {%0,%1,%2,%3};"
        : "+f"(d[0]), "+f"(d[1]), "+f"(d[2]), "+f"(d[3])
        : "r"(a[0]), "r"(a[1]), "r"(a[2]), "r"(a[3]), "r"(b0), "r"(b1));
}
__device__ __forceinline__ u64 pk2(float a, float b) {
    u64 r; asm("mov.b64 %0, {%1, %2};" : "=l"(r) : "f"(a), "f"(b)); return r;
}
__device__ __forceinline__ void up2(float& a, float& b, u64 v) {
    asm("mov.b64 {%0, %1}, %2;" : "=f"(a), "=f"(b) : "l"(v));
}
__device__ __forceinline__ u64 mul2(u64 a, u64 b) {
    u64 d; asm("mul.rn.f32x2 %0, %1, %2;" : "=l"(d) : "l"(a), "l"(b)); return d;
}
__device__ __forceinline__ u64 fma2(u64 a, u64 b, u64 c) {
    u64 d; asm("fma.rn.f32x2 %0, %1, %2, %3;" : "=l"(d) : "l"(a), "l"(b), "l"(c)); return d;
}

// ---------------- fp16 1-product HMMA GEMM, 128x128 tile, 4-stage ring ----------------
#define PITCH 80

__global__ __launch_bounds__(256, 2) void gemm_f16(
    const u16* __restrict__ Ah, const u16* __restrict__ Bh,
    float* __restrict__ C, int N, int K)
{
    constexpr int ABYT = 128 * PITCH;
    constexpr int STAGE = 2 * ABYT;

    extern __shared__ __align__(16) char smem[];
    const u32 sb = smem_u32(smem);

    const int tid = threadIdx.x;
    const long brow = (long)blockIdx.y * 128;
    const long bcol = (long)blockIdx.x * 128;

    const int wid  = tid >> 5;
    const int lane = tid & 31;
    const int wm = wid & 1;
    const int wn = wid >> 1;

    const int a_row  = lane & 15;
    const int a_colb = (lane >> 4) * 16;
    const int q = lane >> 3;
    const int b_n  = (lane & 7) + ((q >> 1) << 3);
    const int b_kb = (q & 1) * 16;

    const u32 aAddr = sb + (u32)((wm*64 + a_row) * PITCH + a_colb);
    const u32 bAddr = sb + ABYT + (u32)((wn*32 + b_n) * PITCH + b_kb);

    float acc[4][4][4];
    #pragma unroll
    for (int i = 0; i < 4; i++)
        #pragma unroll
        for (int j = 0; j < 4; j++)
            #pragma unroll
            for (int v = 0; v < 4; v++) acc[i][j][v] = 0.0f;

    const int nst = K >> 5;

    auto load_stage = [&](int s) {
        const u32 base = sb + (u32)((s & 3) * STAGE);
        const int kt = s << 5;
        #pragma unroll
        for (int i = tid; i < 512; i += 256) {
            int r = i >> 2, ch = i & 3;
            u32 d = base + (u32)(r * PITCH + ch * 16);
            cp16(d, Ah + (brow + r) * (long)K + kt + ch * 8);
            cp16(d + ABYT, Bh + (bcol + r) * (long)K + kt + ch * 8);
        }
        cp_commit();
    };

    load_stage(0);
    load_stage(1);
    load_stage(2);

    for (int s = 0; s < nst; s++) {
        const int rem = nst - 1 - s;
        if (rem >= 2)      asm volatile("cp.async.wait_group 2;" ::: "memory");
        else if (rem == 1) asm volatile("cp.async.wait_group 1;" ::: "memory");
        else               asm volatile("cp.async.wait_group 0;" ::: "memory");
        __syncthreads();
        if (s + 3 < nst) load_stage(s + 3);

        const u32 boff = (u32)((s & 3) * STAGE);
        #pragma unroll
        for (int kk = 0; kk < 2; kk++) {
            const u32 kadd = kk * 32;
            u32 bh[2][4];
            ldsm4(bh[0], bAddr + boff + kadd);
            ldsm4(bh[1], bAddr + boff + kadd + 16*PITCH);
            #pragma unroll
            for (int mt = 0; mt < 4; mt++) {
                u32 ah[4];
                ldsm4(ah, aAddr + boff + kadd + (u32)(mt*16*PITCH));
                #pragma unroll
                for (int nt = 0; nt < 4; nt++) {
                    const int p = nt >> 1, h = nt & 1;
                    mma_f16(acc[mt][nt], ah, bh[p][2*h], bh[p][2*h+1]);
                }
            }
        }
        // no trailing sync: top-of-next-stage sync orders compute(s) before load(s+4)
    }

    #pragma unroll
    for (int mt = 0; mt < 4; mt++) {
        long r0 = brow + wm*64 + mt*16 + (lane >> 2);
        long cc = bcol + wn*32 + ((lane & 3) << 1);
        #pragma unroll
        for (int nt = 0; nt < 4; nt++) {
            float2 v0 = make_float2(acc[mt][nt][0], acc[mt][nt][1]);
            float2 v1 = make_float2(acc[mt][nt][2], acc[mt][nt][3]);
            *(float2*)&C[r0 * N + cc + nt*8]     = v0;
            *(float2*)&C[(r0+8) * N + cc + nt*8] = v1;
        }
    }
}

// ---------------- wx GEMM: 64x64 tile, bf16 3-product ----------------
__global__ __launch_bounds__(256, 3) void gemm_wx64(
    const u16* __restrict__ Ah, const u16* __restrict__ Al,
    const u16* __restrict__ Bh, const u16* __restrict__ Bl,
    float* __restrict__ C, int N, int K)
{
    constexpr int ABYT = 64 * PITCH;
    constexpr int OFF_AL = ABYT;
    constexpr int OFF_BH = 2 * ABYT;
    constexpr int OFF_BL = 3 * ABYT;
    constexpr int STAGE = 4 * ABYT;

    extern __shared__ __align__(16) char smem[];
    const u32 sb = smem_u32(smem);

    const int tid = threadIdx.x;
    const long brow = (long)blockIdx.y * 64;

    const int wid  = tid >> 5;
    const int lane = tid & 31;
    const int wm = wid & 1;
    const int wn = wid >> 1;

    const int a_row  = lane & 15;
    const int a_colb = (lane >> 4) * 16;
    const int q = lane >> 3;
    const int b_n  = (lane & 7) + ((q >> 1) << 3);
    const int b_kb = (q & 1) * 16;

    const u32 aAddrH = sb + (u32)((wm*32 + a_row) * PITCH + a_colb);
    const u32 aAddrL = aAddrH + OFF_AL;
    const u32 bAddrH = sb + OFF_BH + (u32)((wn*16 + b_n) * PITCH + b_kb);
    const u32 bAddrL = bAddrH + ABYT;

    float acc[2][2][4];
    #pragma unroll
    for (int i = 0; i < 2; i++)
        #pragma unroll
        for (int j = 0; j < 2; j++)
            #pragma unroll
            for (int v = 0; v < 4; v++) acc[i][j][v] = 0.0f;

    const int nst = K >> 5;

    auto load_stage = [&](int s) {
        const u32 base = sb + (u32)((s % 3) * STAGE);
        const int kt = s << 5;
        {
            int i = tid;
            int r = i >> 2, ch = i & 3;
            u32 d = base + (u32)(r * PITCH + ch * 16);
            long g = (brow + r) * (long)K + kt + ch * 8;
            cp16(d, Ah + g);
            cp16(d + OFF_AL, Al + g);
            long gb = (long)r * K + kt + ch * 8;
            cp16(d + OFF_BH, Bh + gb);
            cp16(d + OFF_BL, Bl + gb);
        }
        cp_commit();
    };

    load_stage(0);
    load_stage(1);

    for (int s = 0; s < nst; s++) {
        if (s + 1 < nst) asm volatile("cp.async.wait_group 1;" ::: "memory");
        else             asm volatile("cp.async.wait_group 0;" ::: "memory");
        __syncthreads();
        if (s + 2 < nst) load_stage(s + 2);

        const u32 boff = (u32)((s % 3) * STAGE);
        #pragma unroll
        for (int kk = 0; kk < 2; kk++) {
            const u32 kadd = kk * 32;
            u32 bh[4], bl[4];
            ldsm4(bh, bAddrH + boff + kadd);
            ldsm4(bl, bAddrL + boff + kadd);
            #pragma unroll
            for (int mt = 0; mt < 2; mt++) {
                u32 ah[4], al[4];
                ldsm4(ah, aAddrH + boff + kadd + (u32)(mt*16*PITCH));
                ldsm4(al, aAddrL + boff + kadd + (u32)(mt*16*PITCH));
                #pragma unroll
                for (int nt = 0; nt < 2; nt++) {
                    mma_bf16(acc[mt][nt], ah, bh[2*nt], bh[2*nt+1]);
                    mma_bf16(acc[mt][nt], ah, bl[2*nt], bl[2*nt+1]);
                    mma_bf16(acc[mt][nt], al, bh[2*nt], bh[2*nt+1]);
                }
            }
        }
    }

    #pragma unroll
    for (int mt = 0; mt < 2; mt++) {
        long r0 = brow + wm*32 + mt*16 + (lane >> 2);
        long cc = wn*16 + ((lane & 3) << 1);
        #pragma unroll
        for (int nt = 0; nt < 2; nt++) {
            float2 v0 = make_float2(acc[mt][nt][0], acc[mt][nt][1]);
            float2 v1 = make_float2(acc[mt][nt][2], acc[mt][nt][3]);
            *(float2*)&C[r0 * N + cc + nt*8]     = v0;
            *(float2*)&C[(r0+8) * N + cc + nt*8] = v1;
        }
    }
}

// ---------------- operand prep kernels ----------------
__global__ __launch_bounds__(256) void convert_f16(
    const float* __restrict__ src, __half* __restrict__ dst, int n)
{
    int i = blockIdx.x * 256 + threadIdx.x;
    if (i < n) dst[i] = __float2half_rn(src[i]);
}

__global__ void transpose_f16(
    const float* __restrict__ src, __half* __restrict__ dst, int R, int C)
{
    __shared__ float t[32][33];
    int c0 = blockIdx.x * 32, r0 = blockIdx.y * 32;
    int tx = threadIdx.x, ty = threadIdx.y;
    #pragma unroll
    for (int i = 0; i < 32; i += 8)
        t[ty + i][tx] = src[(long)(r0 + ty + i) * C + c0 + tx];
    __syncthreads();
    #pragma unroll
    for (int i = 0; i < 32; i += 8)
        dst[(long)(c0 + ty + i) * R + r0 + tx] = __float2half_rn(t[tx][ty + i]);
}

__global__ void transpose_split_bf16(
    const float* __restrict__ src, bf16* __restrict__ hi, bf16* __restrict__ lo,
    int R, int C, int Cpad)
{
    __shared__ float t[32][33];
    int c0 = blockIdx.x * 32, r0 = blockIdx.y * 32;
    int tx = threadIdx.x, ty = threadIdx.y;
    #pragma unroll
    for (int i = 0; i < 32; i += 8) {
        int c = c0 + tx;
        float v = (c < C) ? src[(long)(r0 + ty + i) * C + c] : 0.0f;
        t[ty + i][tx] = v;
    }
    __syncthreads();
    #pragma unroll
    for (int i = 0; i < 32; i += 8) {
        int oc = c0 + ty + i;
        if (oc < Cpad) {
            float v = t[tx][ty + i];
            bf16 h = __float2bfloat16_rn(v);
            hi[(long)oc * R + r0 + tx] = h;
            lo[(long)oc * R + r0 + tx] = __float2bfloat16_rn(v - __bfloat162float(h));
        }
    }
}

// ---------------- tiled depthwise causal conv (K=4) + SiLU ----------------
// block: 256 threads = one d-column each; tile = 32 l-rows; smem slab 35 x 256.
#define CONV_TL 32
__global__ __launch_bounds__(256) void conv_silu_tiled(
    const float* __restrict__ xz, const float* __restrict__ conv_w,
    const float* __restrict__ conv_b, float* __restrict__ xc,
    bf16* __restrict__ xch, bf16* __restrict__ xcl)
{
    __shared__ float sx[CONV_TL + 3][256];
    const int tid = threadIdx.x;
    const int d0 = blockIdx.x * 256;
    const int l0 = blockIdx.y * CONV_TL;
    const int b  = blockIdx.z;
    const int d  = d0 + tid;

    #pragma unroll 5
    for (int r = 0; r < CONV_TL + 3; r++) {
        int l = l0 - 3 + r;
        sx[r][tid] = (l >= 0) ? xz[((long)(b * LL + l)) * (2*DINNER) + d] : 0.0f;
    }
    __syncthreads();

    const float4 wv = *(const float4*)&conv_w[d * DCONV];
    const float bias = conv_b[d];

    #pragma unroll 4
    for (int j = 0; j < CONV_TL; j++) {
        float acc = bias;
        acc += sx[j+0][tid] * wv.x;
        acc += sx[j+1][tid] * wv.y;
        acc += sx[j+2][tid] * wv.z;
        acc += sx[j+3][tid] * wv.w;
        float s = acc / (1.0f + __expf(-acc));
        long idx = ((long)(b * LL + l0 + j)) * DINNER + d;
        xc[idx] = s;
        bf16 h = __float2bfloat16_rn(s);
        xch[idx] = h;
        xcl[idx] = __float2bfloat16_rn(s - __bfloat162float(h));
    }
}

// ---------------- coefficients + per-chunk a-products (merged) ----------------
// grid (NCH, BB); 256 threads handle 128 rows x 16 n.
__global__ __launch_bounds__(256) void coef_ptot(
    const float* __restrict__ xdbl, const float* __restrict__ A_log,
    float* __restrict__ coef, float* __restrict__ ptot)
{
    __shared__ float sa[CHL][16];
    const int c = blockIdx.x, b = blockIdx.y, tid = threadIdx.x;
    const int n = tid & 15;
    const long lbase = (long)b * LL + c * CHL;
    const float Aneg = -expf(A_log[n]);

    for (int r0 = 0; r0 < CHL; r0 += 16) {
        int rloc = r0 + (tid >> 4);
        long r = lbase + rloc;
        const float* xr = xdbl + r * 64;
        float v = xr[0];
        float delta = (v > 20.0f) ? v : log1pf(expf(v));
        float abar = expf(delta * Aneg);
        float* o = coef + r * 48;
        o[n]      = abar;
        o[16 + n] = delta * xr[1 + n];
        o[32 + n] = xr[17 + n];
        sa[rloc][n] = abar;
    }
    __syncthreads();
    if (tid < 16) {
        float p = 1.0f;
        #pragma unroll 8
        for (int l = 0; l < CHL; l++) p *= sa[l][tid];
        ptot[(b*NCH + c)*16 + tid] = p;
    }
}

// ---------------- scan pass 1: local chunk scan from h=0, store h_end ----------------
__global__ __launch_bounds__(256) void scan_pass1(
    const float* __restrict__ coef, const float* __restrict__ xc,
    float* __restrict__ hend)
{
    __shared__ float sca[CHL*32];
    int b = blockIdx.z, c = blockIdx.y, tid = threadIdx.x;
    int d = blockIdx.x * 256 + tid;
    long lbase = (long)b * LL + c * CHL;
    for (int i = tid; i < CHL*32; i += 256) {
        int row = i >> 5, j = i & 31;
        sca[i] = coef[(lbase + row)*48 + j];
    }
    __syncthreads();
    u64 h2[8];
    #pragma unroll
    for (int j = 0; j < 8; j++) h2[j] = 0ull;
    for (int l = 0; l < CHL; l++) {
        float xv = xc[(lbase + l)*DINNER + d];
        u64 xx = pk2(xv, xv);
        const u64* ap = (const u64*)&sca[l*32];
        #pragma unroll
        for (int j = 0; j < 8; j++) {
            u64 u = mul2(ap[8+j], xx);
            h2[j] = fma2(ap[j], h2[j], u);
        }
    }
    float* o = hend + (((long)(b*NCH + c) * DINNER) + d) * 16;
    #pragma unroll
    for (int j = 0; j < 8; j++) {
        float x0, x1; up2(x0, x1, h2[j]);
        o[2*j] = x0; o[2*j+1] = x1;
    }
}

// ---------------- scan pass 2: combine chunk carries ----------------
__global__ __launch_bounds__(256) void scan_pass2(
    const float* __restrict__ hend, const float* __restrict__ ptot,
    float* __restrict__ hstart)
{
    long idx = (long)blockIdx.x * 256 + threadIdx.x;
    int n = (int)(idx & 15);
    int d = (int)((idx >> 4) & (DINNER-1));
    int b = (int)(idx >> 15);
    float hs = 0.0f;
    for (int c = 0; c < NCH; c++) {
        long o = (((long)(b*NCH + c) * DINNER) + d) * 16 + n;
        hstart[o] = hs;
        hs = ptot[(b*NCH + c)*16 + n] * hs + hend[o];
    }
}

// ---------------- scan pass 3: rerun recurrence from h_start + skip + gate ----------------
__global__ __launch_bounds__(256) void scan_pass3(
    const float* __restrict__ coef, const float* __restrict__ hstart,
    const float* __restrict__ xc, const float* __restrict__ xz,
    const float* __restrict__ Dp, __half* __restrict__ yh)
{
    __shared__ float sc[CHL*48];
    int b = blockIdx.z, c = blockIdx.y, tid = threadIdx.x;
    int d = blockIdx.x * 256 + tid;
    long lbase = (long)b * LL + c * CHL;
    for (int i = tid; i < CHL*48; i += 256)
        sc[i] = coef[lbase*48 + i];
    __syncthreads();

    u64 h2[8];
    const u64* hsp = (const u64*)(hstart + (((long)(b*NCH + c) * DINNER) + d) * 16);
    #pragma unroll
    for (int j = 0; j < 8; j++) h2[j] = hsp[j];   // init from chunk-start state (exact)
    float Dd = Dp[d];

    for (int l = 0; l < CHL; l++) {
        long row = lbase + l;
        float xv = xc[row*DINNER + d];
        float zv = xz[row*(2*DINNER) + DINNER + d];
        u64 xx = pk2(xv, xv);
        const u64* ap = (const u64*)&sc[l*48];   // a:0..7  bb:8..15  C:16..23
        u64 y2 = 0ull;
        #pragma unroll
        for (int j = 0; j < 8; j++) {
            u64 u = mul2(ap[8+j], xx);
            h2[j] = fma2(ap[j], h2[j], u);
            y2 = fma2(h2[j], ap[16+j], y2);
        }
        float y0, y1;
        up2(y0, y1, y2);
        float y = y0 + y1 + xv * Dd;
        float sg = zv / (1.0f + __expf(-zv));
        yh[row*DINNER + d] = __float2half_rn(y * sg);
    }
}

// ---------------- launch ----------------
extern "C" void kernel_launch(void* const* d_in, const int* in_sizes, int n_in,
                              void* d_out, int out_size)
{
    const float* x       = (const float*)d_in[0];
    const float* W_in    = (const float*)d_in[1];
    const float* conv_w  = (const float*)d_in[2];
    const float* conv_b  = (const float*)d_in[3];
    const float* W_x     = (const float*)d_in[4];
    const float* A_log   = (const float*)d_in[5];
    const float* D_param = (const float*)d_in[6];
    const float* W_out   = (const float*)d_in[7];
    float* out = (float*)d_out;

    float *xz, *xc, *coefp, *xdbl, *ptot, *hend, *hstart;
    __half *xh, *winT, *woutT, *yh;
    bf16 *xch, *xcl, *wxh, *wxl;
    cudaGetSymbolAddress((void**)&xz,    g_xz);
    cudaGetSymbolAddress((void**)&xc,    g_xc);
    cudaGetSymbolAddress((void**)&coefp, g_coef);
    cudaGetSymbolAddress((void**)&xdbl,  g_xdbl);
    cudaGetSymbolAddress((void**)&ptot,  g_ptot);
    cudaGetSymbolAddress((void**)&hend,  g_hend);
    cudaGetSymbolAddress((void**)&hstart,g_hstart);
    cudaGetSymbolAddress((void**)&xh,    g_xh);
    cudaGetSymbolAddress((void**)&winT,  g_winT);
    cudaGetSymbolAddress((void**)&woutT, g_woutT);
    cudaGetSymbolAddress((void**)&xch,   g_xch);
    cudaGetSymbolAddress((void**)&xcl,   g_xcl);
    cudaGetSymbolAddress((void**)&wxh,   g_wxT_h);
    cudaGetSymbolAddress((void**)&wxl,   g_wxT_l);
    cudaGetSymbolAddress((void**)&yh,    g_yh);

    const int SMEM1 = 4 * (2*128*80);            // 81920
    const int SMEMW = 3 * (4*64*80);             // 61440
    cudaFuncSetAttribute((const void*)gemm_f16,  cudaFuncAttributeMaxDynamicSharedMemorySize, SMEM1);
    cudaFuncSetAttribute((const void*)gemm_wx64, cudaFuncAttributeMaxDynamicSharedMemorySize, SMEMW);

    // 1) operand prep
    convert_f16<<<(M_ROWS*DMODEL)/256, 256>>>(x, xh, M_ROWS*DMODEL);
    transpose_f16<<<dim3(4096/32, 1024/32), dim3(32,8)>>>(W_in,  winT,  1024, 4096);
    transpose_f16<<<dim3(1024/32, 2048/32), dim3(32,8)>>>(W_out, woutT, 2048, 1024);
    transpose_split_bf16<<<dim3(64/32, 2048/32), dim3(32,8)>>>(W_x, wxh, wxl, 2048, 33, 64);

    // 2) xz = x @ W_in  (fp16 1-product)
    gemm_f16<<<dim3(4096/128, 8192/128), 256, SMEM1>>>(
        (const u16*)xh, (const u16*)winT, xz, 4096, 1024);

    // 3) conv + silu (smem-tiled)
    conv_silu_tiled<<<dim3(DINNER/256, LL/CONV_TL, BB), 256>>>(
        xz, conv_w, conv_b, xc, xch, xcl);

    // 4) x_dbl = xc @ W_x  (bf16 3-product)
    gemm_wx64<<<dim3(1, 8192/64), 256, SMEMW>>>(
        (const u16*)xch, (const u16*)xcl, (const u16*)wxh, (const u16*)wxl, xdbl, 64, 2048);

    // 5) coefficients + chunk products (merged)
    coef_ptot<<<dim3(NCH, BB), 256>>>(xdbl, A_log, coefp, ptot);

    // 6) chunked parallel scan
    scan_pass1<<<dim3(DINNER/256, NCH, BB), 256>>>(coefp, xc, hend);
    scan_pass2<<<(BB*DINNER*DSTATE)/256, 256>>>(hend, ptot, hstart);
    scan_pass3<<<dim3(DINNER/256, NCH, BB), 256>>>(coefp, hstart, xc, xz, D_param, yh);

    // 7) out = y @ W_out  (fp16 1-product)
    gemm_f16<<<dim3(1024/128, 8192/128), 256, SMEM1>>>(
        (const u16*)yh, (const u16*)woutT, out, 1024, 2048);
}

// round 8
// speedup vs baseline: 5.2854x; 1.0098x over previous
#include <cuda_runtime.h>
#include <cuda_bf16.h>
#include <cuda_fp16.h>
#include <math.h>
#include <stdint.h>

#define BB 4
#define LL 2048
#define DMODEL 1024
#define DSTATE 16
#define DCONV 4
#define DINNER 2048
#define M_ROWS (BB*LL)            // 8192
#define NCH 16                    // chunks per sequence
#define CHL 128                   // chunk length

typedef unsigned int u32;
typedef unsigned long long u64;
typedef __nv_bfloat16 bf16;
typedef uint16_t u16;

// ---------------- scratch (device globals) ----------------
__device__ __align__(16) __half g_xzh[(size_t)M_ROWS * (2*DINNER)];   // fp16 xz (64MB)
__device__ __align__(16) __half g_xh[(size_t)M_ROWS * DMODEL];
__device__ __align__(16) __half g_winT[(size_t)(2*DINNER) * DMODEL];
__device__ __align__(16) bf16  g_xch[(size_t)M_ROWS * DINNER];
__device__ __align__(16) bf16  g_xcl[(size_t)M_ROWS * DINNER];
__device__ __align__(16) bf16  g_wxT_h[64 * DINNER];
__device__ __align__(16) bf16  g_wxT_l[64 * DINNER];
__device__ __align__(16) float g_xdbl[(size_t)M_ROWS * 64];
__device__ __align__(16) float g_coef[(size_t)M_ROWS * 48];
__device__ __align__(16) float g_ptot[BB * NCH * DSTATE];
__device__ __align__(16) float g_hend[(size_t)BB * NCH * DINNER * DSTATE];
__device__ __align__(16) float g_hstart[(size_t)BB * NCH * DINNER * DSTATE];
__device__ __align__(16) __half g_yh[(size_t)M_ROWS * DINNER];
__device__ __align__(16) __half g_woutT[(size_t)DMODEL * DINNER];

// ---------------- PTX helpers (BASE PTX ONLY) ----------------
__device__ __forceinline__ u32 smem_u32(const void* p) {
    u32 a; asm("{ .reg .u64 t; cvta.to.shared.u64 t, %1; cvt.u32.u64 %0, t; }" : "=r"(a) : "l"(p));
    return a;
}
__device__ __forceinline__ void cp16(u32 dst, const void* src) {
    asm volatile("cp.async.cg.shared.global [%0], [%1], 16;" :: "r"(dst), "l"(src));
}
__device__ __forceinline__ void cp_commit() {
    asm volatile("cp.async.commit_group;" ::: "memory");
}
__device__ __forceinline__ void ldsm4(u32* r, u32 addr) {
    asm volatile("ldmatrix.sync.aligned.m8n8.x4.shared.b16 {%0,%1,%2,%3}, [%4];"
                 : "=r"(r[0]), "=r"(r[1]), "=r"(r[2]), "=r"(r[3]) : "r"(addr));
}
__device__ __forceinline__ void mma_bf16(float* d, const u32* a, const u32 b0, const u32 b1) {
    asm volatile(
        "mma.sync.aligned.m16n8k16.row.col.f32.bf16.bf16.f32 "
        "{%0,%1,%2,%3}, {%4,%5,%6,%7}, {%8,%9}, {%0,%1,%2,%3};"
        : "+f"(d[0]), "+f"(d[1]), "+f"(d[2]), "+f"(d[3])
        : "r"(a[0]), "r"(a[1]), "r"(a[2]), "r"(a[3]), "r"(b0), "r"(b1));
}
__device__ __forceinline__ void mma_f16(float* d, const u32* a, const u32 b0, const u32 b1) {
    asm volatile(
        "mma.sync.aligned.m16n8k16.row.col.f32.f16.f16.f32 "
        "{%0,%1,%2,%3}, {%4,%5,%6,%7}, {%8,%9}, {%0,%1,%2,%3};"
        : "+f"(d[0]), "+f"(d[1]), "+f"(d[2]), "+f"(d[3])
        : "r"(a[0]), "r"(a[1]), "r"(a[2]), "r"(a[3]), "r"(b0), "r"(b1));
}
__device__ __forceinline__ u64 pk2(float a, float b) {
    u64 r; asm("mov.b64 %0, {%1, %2};" : "=l"(r) : "f"(a), "f"(b)); return r;
}
__device__ __forceinline__ void up2(float& a, float& b, u64 v) {
    asm("mov.b64 {%0, %1}, %2;" : "=f"(a), "=f"(b) : "l"(v));
}
__device__ __forceinline__ u64 mul2(u64 a, u64 b) {
    u64 d; asm("mul.rn.f32x2 %0, %1, %2;" : "=l"(d) : "l"(a), "l"(b)); return d;
}
__device__ __forceinline__ u64 fma2(u64 a, u64 b, u64 c) {
    u64 d; asm("fma.rn.f32x2 %0, %1, %2, %3;" : "=l"(d) : "l"(a), "l"(b), "l"(c)); return d;
}

// ---------------- fp16 1-product HMMA GEMM, 128x128 tile, 4-stage ring ----------------
#define PITCH 80

template<typename OutT>
__global__ __launch_bounds__(256, 2) void gemm_f16(
    const u16* __restrict__ Ah, const u16* __restrict__ Bh,
    OutT* __restrict__ C, int N, int K)
{
    constexpr int ABYT = 128 * PITCH;
    constexpr int STAGE = 2 * ABYT;

    extern __shared__ __align__(16) char smem[];
    const u32 sb = smem_u32(smem);

    const int tid = threadIdx.x;
    const long brow = (long)blockIdx.y * 128;
    const long bcol = (long)blockIdx.x * 128;

    const int wid  = tid >> 5;
    const int lane = tid & 31;
    const int wm = wid & 1;
    const int wn = wid >> 1;

    const int a_row  = lane & 15;
    const int a_colb = (lane >> 4) * 16;
    const int q = lane >> 3;
    const int b_n  = (lane & 7) + ((q >> 1) << 3);
    const int b_kb = (q & 1) * 16;

    const u32 aAddr = sb + (u32)((wm*64 + a_row) * PITCH + a_colb);
    const u32 bAddr = sb + ABYT + (u32)((wn*32 + b_n) * PITCH + b_kb);

    float acc[4][4][4];
    #pragma unroll
    for (int i = 0; i < 4; i++)
        #pragma unroll
        for (int j = 0; j < 4; j++)
            #pragma unroll
            for (int v = 0; v < 4; v++) acc[i][j][v] = 0.0f;

    const int nst = K >> 5;

    auto load_stage = [&](int s) {
        const u32 base = sb + (u32)((s & 3) * STAGE);
        const int kt = s << 5;
        #pragma unroll
        for (int i = tid; i < 512; i += 256) {
            int r = i >> 2, ch = i & 3;
            u32 d = base + (u32)(r * PITCH + ch * 16);
            cp16(d, Ah + (brow + r) * (long)K + kt + ch * 8);
            cp16(d + ABYT, Bh + (bcol + r) * (long)K + kt + ch * 8);
        }
        cp_commit();
    };

    load_stage(0);
    load_stage(1);
    load_stage(2);

    for (int s = 0; s < nst; s++) {
        const int rem = nst - 1 - s;
        if (rem >= 2)      asm volatile("cp.async.wait_group 2;" ::: "memory");
        else if (rem == 1) asm volatile("cp.async.wait_group 1;" ::: "memory");
        else               asm volatile("cp.async.wait_group 0;" ::: "memory");
        __syncthreads();
        if (s + 3 < nst) load_stage(s + 3);

        const u32 boff = (u32)((s & 3) * STAGE);
        #pragma unroll
        for (int kk = 0; kk < 2; kk++) {
            const u32 kadd = kk * 32;
            u32 bh[2][4];
            ldsm4(bh[0], bAddr + boff + kadd);
            ldsm4(bh[1], bAddr + boff + kadd + 16*PITCH);
            #pragma unroll
            for (int mt = 0; mt < 4; mt++) {
                u32 ah[4];
                ldsm4(ah, aAddr + boff + kadd + (u32)(mt*16*PITCH));
                #pragma unroll
                for (int nt = 0; nt < 4; nt++) {
                    const int p = nt >> 1, h = nt & 1;
                    mma_f16(acc[mt][nt], ah, bh[p][2*h], bh[p][2*h+1]);
                }
            }
        }
    }

    #pragma unroll
    for (int mt = 0; mt < 4; mt++) {
        long r0 = brow + wm*64 + mt*16 + (lane >> 2);
        long cc = bcol + wn*32 + ((lane & 3) << 1);
        #pragma unroll
        for (int nt = 0; nt < 4; nt++) {
            if (sizeof(OutT) == 2) {
                __half2* p0 = (__half2*)((__half*)C + r0 * N + cc + nt*8);
                __half2* p1 = (__half2*)((__half*)C + (r0+8) * N + cc + nt*8);
                *p0 = __floats2half2_rn(acc[mt][nt][0], acc[mt][nt][1]);
                *p1 = __floats2half2_rn(acc[mt][nt][2], acc[mt][nt][3]);
            } else {
                float2 v0 = make_float2(acc[mt][nt][0], acc[mt][nt][1]);
                float2 v1 = make_float2(acc[mt][nt][2], acc[mt][nt][3]);
                *(float2*)((float*)C + r0 * N + cc + nt*8)     = v0;
                *(float2*)((float*)C + (r0+8) * N + cc + nt*8) = v1;
            }
        }
    }
}

// ---------------- wx GEMM: 64x64 tile, bf16 3-product ----------------
__global__ __launch_bounds__(256, 3) void gemm_wx64(
    const u16* __restrict__ Ah, const u16* __restrict__ Al,
    const u16* __restrict__ Bh, const u16* __restrict__ Bl,
    float* __restrict__ C, int N, int K)
{
    constexpr int ABYT = 64 * PITCH;
    constexpr int OFF_AL = ABYT;
    constexpr int OFF_BH = 2 * ABYT;
    constexpr int OFF_BL = 3 * ABYT;
    constexpr int STAGE = 4 * ABYT;

    extern __shared__ __align__(16) char smem[];
    const u32 sb = smem_u32(smem);

    const int tid = threadIdx.x;
    const long brow = (long)blockIdx.y * 64;

    const int wid  = tid >> 5;
    const int lane = tid & 31;
    const int wm = wid & 1;
    const int wn = wid >> 1;

    const int a_row  = lane & 15;
    const int a_colb = (lane >> 4) * 16;
    const int q = lane >> 3;
    const int b_n  = (lane & 7) + ((q >> 1) << 3);
    const int b_kb = (q & 1) * 16;

    const u32 aAddrH = sb + (u32)((wm*32 + a_row) * PITCH + a_colb);
    const u32 aAddrL = aAddrH + OFF_AL;
    const u32 bAddrH = sb + OFF_BH + (u32)((wn*16 + b_n) * PITCH + b_kb);
    const u32 bAddrL = bAddrH + ABYT;

    float acc[2][2][4];
    #pragma unroll
    for (int i = 0; i < 2; i++)
        #pragma unroll
        for (int j = 0; j < 2; j++)
            #pragma unroll
            for (int v = 0; v < 4; v++) acc[i][j][v] = 0.0f;

    const int nst = K >> 5;

    auto load_stage = [&](int s) {
        const u32 base = sb + (u32)((s % 3) * STAGE);
        const int kt = s << 5;
        {
            int i = tid;
            int r = i >> 2, ch = i & 3;
            u32 d = base + (u32)(r * PITCH + ch * 16);
            long g = (brow + r) * (long)K + kt + ch * 8;
            cp16(d, Ah + g);
            cp16(d + OFF_AL, Al + g);
            long gb = (long)r * K + kt + ch * 8;
            cp16(d + OFF_BH, Bh + gb);
            cp16(d + OFF_BL, Bl + gb);
        }
        cp_commit();
    };

    load_stage(0);
    load_stage(1);

    for (int s = 0; s < nst; s++) {
        if (s + 1 < nst) asm volatile("cp.async.wait_group 1;" ::: "memory");
        else             asm volatile("cp.async.wait_group 0;" ::: "memory");
        __syncthreads();
        if (s + 2 < nst) load_stage(s + 2);

        const u32 boff = (u32)((s % 3) * STAGE);
        #pragma unroll
        for (int kk = 0; kk < 2; kk++) {
            const u32 kadd = kk * 32;
            u32 bh[4], bl[4];
            ldsm4(bh, bAddrH + boff + kadd);
            ldsm4(bl, bAddrL + boff + kadd);
            #pragma unroll
            for (int mt = 0; mt < 2; mt++) {
                u32 ah[4], al[4];
                ldsm4(ah, aAddrH + boff + kadd + (u32)(mt*16*PITCH));
                ldsm4(al, aAddrL + boff + kadd + (u32)(mt*16*PITCH));
                #pragma unroll
                for (int nt = 0; nt < 2; nt++) {
                    mma_bf16(acc[mt][nt], ah, bh[2*nt], bh[2*nt+1]);
                    mma_bf16(acc[mt][nt], ah, bl[2*nt], bl[2*nt+1]);
                    mma_bf16(acc[mt][nt], al, bh[2*nt], bh[2*nt+1]);
                }
            }
        }
    }

    #pragma unroll
    for (int mt = 0; mt < 2; mt++) {
        long r0 = brow + wm*32 + mt*16 + (lane >> 2);
        long cc = wn*16 + ((lane & 3) << 1);
        #pragma unroll
        for (int nt = 0; nt < 2; nt++) {
            float2 v0 = make_float2(acc[mt][nt][0], acc[mt][nt][1]);
            float2 v1 = make_float2(acc[mt][nt][2], acc[mt][nt][3]);
            *(float2*)&C[r0 * N + cc + nt*8]     = v0;
            *(float2*)&C[(r0+8) * N + cc + nt*8] = v1;
        }
    }
}

// ---------------- operand prep kernels ----------------
__global__ __launch_bounds__(256) void convert_f16(
    const float* __restrict__ src, __half* __restrict__ dst, int n)
{
    int i = blockIdx.x * 256 + threadIdx.x;
    if (i < n) dst[i] = __float2half_rn(src[i]);
}

__global__ void transpose_f16(
    const float* __restrict__ src, __half* __restrict__ dst, int R, int C)
{
    __shared__ float t[32][33];
    int c0 = blockIdx.x * 32, r0 = blockIdx.y * 32;
    int tx = threadIdx.x, ty = threadIdx.y;
    #pragma unroll
    for (int i = 0; i < 32; i += 8)
        t[ty + i][tx] = src[(long)(r0 + ty + i) * C + c0 + tx];
    __syncthreads();
    #pragma unroll
    for (int i = 0; i < 32; i += 8)
        dst[(long)(c0 + ty + i) * R + r0 + tx] = __float2half_rn(t[tx][ty + i]);
}

__global__ void transpose_split_bf16(
    const float* __restrict__ src, bf16* __restrict__ hi, bf16* __restrict__ lo,
    int R, int C, int Cpad)
{
    __shared__ float t[32][33];
    int c0 = blockIdx.x * 32, r0 = blockIdx.y * 32;
    int tx = threadIdx.x, ty = threadIdx.y;
    #pragma unroll
    for (int i = 0; i < 32; i += 8) {
        int c = c0 + tx;
        float v = (c < C) ? src[(long)(r0 + ty + i) * C + c] : 0.0f;
        t[ty + i][tx] = v;
    }
    __syncthreads();
    #pragma unroll
    for (int i = 0; i < 32; i += 8) {
        int oc = c0 + ty + i;
        if (oc < Cpad) {
            float v = t[tx][ty + i];
            bf16 h = __float2bfloat16_rn(v);
            hi[(long)oc * R + r0 + tx] = h;
            lo[(long)oc * R + r0 + tx] = __float2bfloat16_rn(v - __bfloat162float(h));
        }
    }
}

// ---------------- tiled depthwise causal conv (K=4) + SiLU ----------------
#define CONV_TL 32
__global__ __launch_bounds__(256) void conv_silu_tiled(
    const __half* __restrict__ xz, const float* __restrict__ conv_w,
    const float* __restrict__ conv_b,
    bf16* __restrict__ xch, bf16* __restrict__ xcl)
{
    __shared__ float sx[CONV_TL + 3][256];
    const int tid = threadIdx.x;
    const int d0 = blockIdx.x * 256;
    const int l0 = blockIdx.y * CONV_TL;
    const int b  = blockIdx.z;
    const int d  = d0 + tid;

    #pragma unroll 5
    for (int r = 0; r < CONV_TL + 3; r++) {
        int l = l0 - 3 + r;
        sx[r][tid] = (l >= 0) ? __half2float(xz[((long)(b * LL + l)) * (2*DINNER) + d]) : 0.0f;
    }
    __syncthreads();

    const float4 wv = *(const float4*)&conv_w[d * DCONV];
    const float bias = conv_b[d];

    #pragma unroll 4
    for (int j = 0; j < CONV_TL; j++) {
        float acc = bias;
        acc += sx[j+0][tid] * wv.x;
        acc += sx[j+1][tid] * wv.y;
        acc += sx[j+2][tid] * wv.z;
        acc += sx[j+3][tid] * wv.w;
        float s = acc / (1.0f + __expf(-acc));
        long idx = ((long)(b * LL + l0 + j)) * DINNER + d;
        bf16 h = __float2bfloat16_rn(s);
        xch[idx] = h;
        xcl[idx] = __float2bfloat16_rn(s - __bfloat162float(h));
    }
}

// ---------------- coefficients + per-chunk a-products ----------------
__global__ __launch_bounds__(256) void coef_ptot(
    const float* __restrict__ xdbl, const float* __restrict__ A_log,
    float* __restrict__ coef, float* __restrict__ ptot)
{
    __shared__ float sa[CHL][16];
    const int c = blockIdx.x, b = blockIdx.y, tid = threadIdx.x;
    const int n = tid & 15;
    const long lbase = (long)b * LL + c * CHL;
    const float Aneg = -expf(A_log[n]);

    for (int r0 = 0; r0 < CHL; r0 += 16) {
        int rloc = r0 + (tid >> 4);
        long r = lbase + rloc;
        const float* xr = xdbl + r * 64;
        float v = xr[0];
        float delta = (v > 20.0f) ? v : log1pf(expf(v));
        float abar = expf(delta * Aneg);
        float* o = coef + r * 48;
        o[n]      = abar;
        o[16 + n] = delta * xr[1 + n];
        o[32 + n] = xr[17 + n];
        sa[rloc][n] = abar;
    }
    __syncthreads();
    if (tid < 16) {
        float p = 1.0f;
        #pragma unroll 8
        for (int l = 0; l < CHL; l++) p *= sa[l][tid];
        ptot[(b*NCH + c)*16 + tid] = p;
    }
}

// ---------------- scan pass 1: local chunk scan from h=0, store h_end ----------------
__global__ __launch_bounds__(256) void scan_pass1(
    const float* __restrict__ coef, const bf16* __restrict__ xch,
    const bf16* __restrict__ xcl, float* __restrict__ hend)
{
    __shared__ float sca[CHL*32];
    int b = blockIdx.z, c = blockIdx.y, tid = threadIdx.x;
    int d = blockIdx.x * 256 + tid;
    long lbase = (long)b * LL + c * CHL;
    for (int i = tid; i < CHL*32; i += 256) {
        int row = i >> 5, j = i & 31;
        sca[i] = coef[(lbase + row)*48 + j];
    }
    __syncthreads();
    u64 h2[8];
    #pragma unroll
    for (int j = 0; j < 8; j++) h2[j] = 0ull;
    for (int l = 0; l < CHL; l++) {
        long ix = (lbase + l)*DINNER + d;
        float xv = __bfloat162float(xch[ix]) + __bfloat162float(xcl[ix]);
        u64 xx = pk2(xv, xv);
        const u64* ap = (const u64*)&sca[l*32];
        #pragma unroll
        for (int j = 0; j < 8; j++) {
            u64 u = mul2(ap[8+j], xx);
            h2[j] = fma2(ap[j], h2[j], u);
        }
    }
    float* o = hend + (((long)(b*NCH + c) * DINNER) + d) * 16;
    #pragma unroll
    for (int j = 0; j < 8; j++) {
        float x0, x1; up2(x0, x1, h2[j]);
        o[2*j] = x0; o[2*j+1] = x1;
    }
}

// ---------------- scan pass 2: combine chunk carries ----------------
__global__ __launch_bounds__(256) void scan_pass2(
    const float* __restrict__ hend, const float* __restrict__ ptot,
    float* __restrict__ hstart)
{
    long idx = (long)blockIdx.x * 256 + threadIdx.x;
    int n = (int)(idx & 15);
    int d = (int)((idx >> 4) & (DINNER-1));
    int b = (int)(idx >> 15);
    float hs = 0.0f;
    for (int c = 0; c < NCH; c++) {
        long o = (((long)(b*NCH + c) * DINNER) + d) * 16 + n;
        hstart[o] = hs;
        hs = ptot[(b*NCH + c)*16 + n] * hs + hend[o];
    }
}

// ---------------- scan pass 3: rerun recurrence from h_start + skip + gate ----------------
__global__ __launch_bounds__(256) void scan_pass3(
    const float* __restrict__ coef, const float* __restrict__ hstart,
    const bf16* __restrict__ xch, const bf16* __restrict__ xcl,
    const __half* __restrict__ xz, const float* __restrict__ Dp,
    __half* __restrict__ yh)
{
    __shared__ float sc[CHL*48];
    int b = blockIdx.z, c = blockIdx.y, tid = threadIdx.x;
    int d = blockIdx.x * 256 + tid;
    long lbase = (long)b * LL + c * CHL;
    for (int i = tid; i < CHL*48; i += 256)
        sc[i] = coef[lbase*48 + i];
    __syncthreads();

    u64 h2[8];
    const u64* hsp = (const u64*)(hstart + (((long)(b*NCH + c) * DINNER) + d) * 16);
    #pragma unroll
    for (int j = 0; j < 8; j++) h2[j] = hsp[j];
    float Dd = Dp[d];

    for (int l = 0; l < CHL; l++) {
        long row = lbase + l;
        long ix = row*DINNER + d;
        float xv = __bfloat162float(xch[ix]) + __bfloat162float(xcl[ix]);
        float zv = __half2float(xz[row*(2*DINNER) + DINNER + d]);
        u64 xx = pk2(xv, xv);
        const u64* ap = (const u64*)&sc[l*48];
        u64 y2 = 0ull;
        #pragma unroll
        for (int j = 0; j < 8; j++) {
            u64 u = mul2(ap[8+j], xx);
            h2[j] = fma2(ap[j], h2[j], u);
            y2 = fma2(h2[j], ap[16+j], y2);
        }
        float y0, y1;
        up2(y0, y1, y2);
        float y = y0 + y1 + xv * Dd;
        float sg = zv / (1.0f + __expf(-zv));
        yh[ix] = __float2half_rn(y * sg);
    }
}

// ---------------- launch ----------------
extern "C" void kernel_launch(void* const* d_in, const int* in_sizes, int n_in,
                              void* d_out, int out_size)
{
    const float* x       = (const float*)d_in[0];
    const float* W_in    = (const float*)d_in[1];
    const float* conv_w  = (const float*)d_in[2];
    const float* conv_b  = (const float*)d_in[3];
    const float* W_x     = (const float*)d_in[4];
    const float* A_log   = (const float*)d_in[5];
    const float* D_param = (const float*)d_in[6];
    const float* W_out   = (const float*)d_in[7];
    float* out = (float*)d_out;

    float *coefp, *xdbl, *ptot, *hend, *hstart;
    __half *xzh, *xh, *winT, *woutT, *yh;
    bf16 *xch, *xcl, *wxh, *wxl;
    cudaGetSymbolAddress((void**)&xzh,   g_xzh);
    cudaGetSymbolAddress((void**)&coefp, g_coef);
    cudaGetSymbolAddress((void**)&xdbl,  g_xdbl);
    cudaGetSymbolAddress((void**)&ptot,  g_ptot);
    cudaGetSymbolAddress((void**)&hend,  g_hend);
    cudaGetSymbolAddress((void**)&hstart,g_hstart);
    cudaGetSymbolAddress((void**)&xh,    g_xh);
    cudaGetSymbolAddress((void**)&winT,  g_winT);
    cudaGetSymbolAddress((void**)&woutT, g_woutT);
    cudaGetSymbolAddress((void**)&xch,   g_xch);
    cudaGetSymbolAddress((void**)&xcl,   g_xcl);
    cudaGetSymbolAddress((void**)&wxh,   g_wxT_h);
    cudaGetSymbolAddress((void**)&wxl,   g_wxT_l);
    cudaGetSymbolAddress((void**)&yh,    g_yh);

    const int SMEM1 = 4 * (2*128*80);            // 81920
    const int SMEMW = 3 * (4*64*80);             // 61440
    cudaFuncSetAttribute((const void*)gemm_f16<__half>, cudaFuncAttributeMaxDynamicSharedMemorySize, SMEM1);
    cudaFuncSetAttribute((const void*)gemm_f16<float>,  cudaFuncAttributeMaxDynamicSharedMemorySize, SMEM1);
    cudaFuncSetAttribute((const void*)gemm_wx64,        cudaFuncAttributeMaxDynamicSharedMemorySize, SMEMW);

    // Launch order chosen so GEMM1 sits in the ncu profile slot (4th launch).
    // 1) x -> fp16
    convert_f16<<<(M_ROWS*DMODEL)/256, 256>>>(x, xh, M_ROWS*DMODEL);
    // 2) W_in^T fp16
    transpose_f16<<<dim3(4096/32, 1024/32), dim3(32,8)>>>(W_in, winT, 1024, 4096);
    // 3) W_x^T bf16 split
    transpose_split_bf16<<<dim3(64/32, 2048/32), dim3(32,8)>>>(W_x, wxh, wxl, 2048, 33, 64);
    // 4) GEMM1: xz(fp16) = x @ W_in                      <-- profiled slot
    gemm_f16<__half><<<dim3(4096/128, 8192/128), 256, SMEM1>>>(
        (const u16*)xh, (const u16*)winT, xzh, 4096, 1024);
    // 5) W_out^T fp16
    transpose_f16<<<dim3(1024/32, 2048/32), dim3(32,8)>>>(W_out, woutT, 2048, 1024);
    // 6) conv + silu -> bf16 split only
    conv_silu_tiled<<<dim3(DINNER/256, LL/CONV_TL, BB), 256>>>(
        xzh, conv_w, conv_b, xch, xcl);
    // 7) x_dbl = xc @ W_x  (bf16 3-product)
    gemm_wx64<<<dim3(1, 8192/64), 256, SMEMW>>>(
        (const u16*)xch, (const u16*)xcl, (const u16*)wxh, (const u16*)wxl, xdbl, 64, 2048);
    // 8) coefficients + chunk products
    coef_ptot<<<dim3(NCH, BB), 256>>>(xdbl, A_log, coefp, ptot);
    // 9-11) chunked parallel scan
    scan_pass1<<<dim3(DINNER/256, NCH, BB), 256>>>(coefp, xch, xcl, hend);
    scan_pass2<<<(BB*DINNER*DSTATE)/256, 256>>>(hend, ptot, hstart);
    scan_pass3<<<dim3(DINNER/256, NCH, BB), 256>>>(coefp, hstart, xch, xcl, xzh, D_param, yh);
    // 12) out = y @ W_out
    gemm_f16<float><<<dim3(1024/128, 8192/128), 256, SMEM1>>>(
        (const u16*)yh, (const u16*)woutT, out, 1024, 2048);
}

// round 9
// speedup vs baseline: 5.6115x; 1.0617x over previous
#include <cuda_runtime.h>
#include <cuda_bf16.h>
#include <cuda_fp16.h>
#include <math.h>
#include <stdint.h>

#define BB 4
#define LL 2048
#define DMODEL 1024
#define DSTATE 16
#define DCONV 4
#define DINNER 2048
#define M_ROWS (BB*LL)            // 8192
#define NCH 16
#define CHL 128

typedef unsigned int u32;
typedef unsigned long long u64;
typedef __nv_bfloat16 bf16;
typedef uint16_t u16;

// ---------------- scratch (device globals) ----------------
__device__ __align__(16) __half g_xzh[(size_t)M_ROWS * (2*DINNER)];
__device__ __align__(16) __half g_xh[(size_t)M_ROWS * DMODEL];
__device__ __align__(16) __half g_winT[(size_t)(2*DINNER) * DMODEL];
__device__ __align__(16) bf16  g_xch[(size_t)M_ROWS * DINNER];
__device__ __align__(16) bf16  g_xcl[(size_t)M_ROWS * DINNER];
__device__ __align__(16) bf16  g_wxT_h[64 * DINNER];
__device__ __align__(16) bf16  g_wxT_l[64 * DINNER];
__device__ __align__(16) float g_xdbl[(size_t)M_ROWS * 64];
__device__ __align__(16) float g_coef[(size_t)M_ROWS * 48];
__device__ __align__(16) float g_ptot[BB * NCH * DSTATE];
__device__ __align__(16) float g_hend[(size_t)BB * NCH * DINNER * DSTATE];
__device__ __align__(16) float g_hstart[(size_t)BB * NCH * DINNER * DSTATE];
__device__ __align__(16) __half g_yh[(size_t)M_ROWS * DINNER];
__device__ __align__(16) __half g_woutT[(size_t)DMODEL * DINNER];

// ---------------- PTX helpers (BASE PTX ONLY) ----------------
__device__ __forceinline__ u32 smem_u32(const void* p) {
    u32 a; asm("{ .reg .u64 t; cvta.to.shared.u64 t, %1; cvt.u32.u64 %0, t; }" : "=r"(a) : "l"(p));
    return a;
}
__device__ __forceinline__ void cp16(u32 dst, const void* src) {
    asm volatile("cp.async.cg.shared.global [%0], [%1], 16;" :: "r"(dst), "l"(src));
}
__device__ __forceinline__ void cp_commit() {
    asm volatile("cp.async.commit_group;" ::: "memory");
}
__device__ __forceinline__ void ldsm4(u32* r, u32 addr) {
    asm volatile("ldmatrix.sync.aligned.m8n8.x4.shared.b16 {%0,%1,%2,%3}, [%4];"
                 : "=r"(r[0]), "=r"(r[1]), "=r"(r[2]), "=r"(r[3]) : "r"(addr));
}
__device__ __forceinline__ void mma_bf16(float* d, const u32* a, const u32 b0, const u32 b1) {
    asm volatile(
        "mma.sync.aligned.m16n8k16.row.col.f32.bf16.bf16.f32 "
        "{%0,%1,%2,%3}, {%4,%5,%6,%7}, {%8,%9}, {%0,%1,%2,%3};"
        : "+f"(d[0]), "+f"(d[1]), "+f"(d[2]), "+f"(d[3])
        : "r"(a[0]), "r"(a[1]), "r"(a[2]), "r"(a[3]), "r"(b0), "r"(b1));
}
__device__ __forceinline__ void mma_f16(float* d, const u32* a, const u32 b0, const u32 b1) {
    asm volatile(
        "mma.sync.aligned.m16n8k16.row.col.f32.f16.f16.f32 "
        "{%0,%1,%2,%3}, {%4,%5,%6,%7}, {%8,%9}, {%0,%1,%2,%3};"
        : "+f"(d[0]), "+f"(d[1]), "+f"(d[2]), "+f"(d[3])
        : "r"(a[0]), "r"(a[1]), "r"(a[2]), "r"(a[3]), "r"(b0), "r"(b1));
}
__device__ __forceinline__ u64 pk2(float a, float b) {
    u64 r; asm("mov.b64 %0, {%1, %2};" : "=l"(r) : "f"(a), "f"(b)); return r;
}
__device__ __forceinline__ void up2(float& a, float& b, u64 v) {
    asm("mov.b64 {%0, %1}, %2;" : "=f"(a), "=f"(b) : "l"(v));
}
__device__ __forceinline__ u64 mul2(u64 a, u64 b) {
    u64 d; asm("mul.rn.f32x2 %0, %1, %2;" : "=l"(d) : "l"(a), "l"(b)); return d;
}
__device__ __forceinline__ u64 fma2(u64 a, u64 b, u64 c) {
    u64 d; asm("fma.rn.f32x2 %0, %1, %2, %3;" : "=l"(d) : "l"(a), "l"(b), "l"(c)); return d;
}

// ---------------- fp16 1-product HMMA GEMM, 128x128 tile ----------------
// BK=64 stages, 3-stage ring, software-pipelined register fragments.
#define PITCH 144   // 64 halfs (128B) + 16B pad; (9r+c)%8 conflict-free for ldmatrix

template<typename OutT>
__global__ __launch_bounds__(256, 2) void gemm_f16(
    const u16* __restrict__ Ah, const u16* __restrict__ Bh,
    OutT* __restrict__ C, int N, int K)
{
    constexpr int ABYT = 128 * PITCH;      // 18432
    constexpr int STAGE = 2 * ABYT;        // 36864

    extern __shared__ __align__(16) char smem[];
    const u32 sb = smem_u32(smem);

    const int tid = threadIdx.x;
    const long brow = (long)blockIdx.y * 128;
    const long bcol = (long)blockIdx.x * 128;

    const int wid  = tid >> 5;
    const int lane = tid & 31;
    const int wm = wid & 1;
    const int wn = wid >> 1;

    const int a_row  = lane & 15;
    const int a_colb = (lane >> 4) * 16;
    const int q = lane >> 3;
    const int b_n  = (lane & 7) + ((q >> 1) << 3);
    const int b_kb = (q & 1) * 16;

    const u32 aAddr = sb + (u32)((wm*64 + a_row) * PITCH + a_colb);
    const u32 bAddr = sb + ABYT + (u32)((wn*32 + b_n) * PITCH + b_kb);

    float acc[4][4][4];
    #pragma unroll
    for (int i = 0; i < 4; i++)
        #pragma unroll
        for (int j = 0; j < 4; j++)
            #pragma unroll
            for (int v = 0; v < 4; v++) acc[i][j][v] = 0.0f;

    const int nst = K >> 6;   // K/64

    auto load_stage = [&](int s) {
        const u32 base = sb + (u32)((s % 3) * STAGE);
        const int kt = s << 6;
        // A: 128 rows x 8 16B-chunks = 1024 ops; B same. 8 ops/thread total each.
        #pragma unroll
        for (int i = tid; i < 1024; i += 256) {
            int r = i >> 3, ch = i & 7;
            u32 d = base + (u32)(r * PITCH + ch * 16);
            cp16(d, Ah + (brow + r) * (long)K + kt + ch * 8);
            cp16(d + ABYT, Bh + (bcol + r) * (long)K + kt + ch * 8);
        }
        cp_commit();
    };

    load_stage(0);
    load_stage(1);

    u32 afr[2][4][4];
    u32 bfr[2][2][4];

    for (int s = 0; s < nst; s++) {
        if (s + 1 < nst) asm volatile("cp.async.wait_group 1;" ::: "memory");
        else             asm volatile("cp.async.wait_group 0;" ::: "memory");
        __syncthreads();
        if (s + 2 < nst) load_stage(s + 2);   // buf (s+2)%3 = (s-1)%3, freed by sync

        const u32 boff = (u32)((s % 3) * STAGE);

        // prefetch frags for kk=0
        ldsm4(bfr[0][0], bAddr + boff);
        ldsm4(bfr[0][1], bAddr + boff + 16*PITCH);
        #pragma unroll
        for (int mt = 0; mt < 4; mt++)
            ldsm4(afr[0][mt], aAddr + boff + (u32)(mt*16*PITCH));

        #pragma unroll
        for (int kk = 0; kk < 4; kk++) {
            const int cur = kk & 1;
            if (kk < 3) {                      // prefetch kk+1 before MMAs of kk
                const u32 kadd = (kk + 1) * 32;
                ldsm4(bfr[cur^1][0], bAddr + boff + kadd);
                ldsm4(bfr[cur^1][1], bAddr + boff + kadd + 16*PITCH);
                #pragma unroll
                for (int mt = 0; mt < 4; mt++)
                    ldsm4(afr[cur^1][mt], aAddr + boff + kadd + (u32)(mt*16*PITCH));
            }
            #pragma unroll
            for (int mt = 0; mt < 4; mt++)
                #pragma unroll
                for (int nt = 0; nt < 4; nt++) {
                    const int p = nt >> 1, h = nt & 1;
                    mma_f16(acc[mt][nt], afr[cur][mt], bfr[cur][p][2*h], bfr[cur][p][2*h+1]);
                }
        }
    }

    #pragma unroll
    for (int mt = 0; mt < 4; mt++) {
        long r0 = brow + wm*64 + mt*16 + (lane >> 2);
        long cc = bcol + wn*32 + ((lane & 3) << 1);
        #pragma unroll
        for (int nt = 0; nt < 4; nt++) {
            if (sizeof(OutT) == 2) {
                __half2* p0 = (__half2*)((__half*)C + r0 * N + cc + nt*8);
                __half2* p1 = (__half2*)((__half*)C + (r0+8) * N + cc + nt*8);
                *p0 = __floats2half2_rn(acc[mt][nt][0], acc[mt][nt][1]);
                *p1 = __floats2half2_rn(acc[mt][nt][2], acc[mt][nt][3]);
            } else {
                float2 v0 = make_float2(acc[mt][nt][0], acc[mt][nt][1]);
                float2 v1 = make_float2(acc[mt][nt][2], acc[mt][nt][3]);
                *(float2*)((float*)C + r0 * N + cc + nt*8)     = v0;
                *(float2*)((float*)C + (r0+8) * N + cc + nt*8) = v1;
            }
        }
    }
}

// ---------------- wx GEMM: 64x64 tile, bf16 3-product (BK=32, PITCH 80) ----------------
#define WPITCH 80

__global__ __launch_bounds__(256, 3) void gemm_wx64(
    const u16* __restrict__ Ah, const u16* __restrict__ Al,
    const u16* __restrict__ Bh, const u16* __restrict__ Bl,
    float* __restrict__ C, int N, int K)
{
    constexpr int ABYT = 64 * WPITCH;
    constexpr int OFF_AL = ABYT;
    constexpr int OFF_BH = 2 * ABYT;
    constexpr int OFF_BL = 3 * ABYT;
    constexpr int STAGE = 4 * ABYT;

    extern __shared__ __align__(16) char smem[];
    const u32 sb = smem_u32(smem);

    const int tid = threadIdx.x;
    const long brow = (long)blockIdx.y * 64;

    const int wid  = tid >> 5;
    const int lane = tid & 31;
    const int wm = wid & 1;
    const int wn = wid >> 1;

    const int a_row  = lane & 15;
    const int a_colb = (lane >> 4) * 16;
    const int q = lane >> 3;
    const int b_n  = (lane & 7) + ((q >> 1) << 3);
    const int b_kb = (q & 1) * 16;

    const u32 aAddrH = sb + (u32)((wm*32 + a_row) * WPITCH + a_colb);
    const u32 aAddrL = aAddrH + OFF_AL;
    const u32 bAddrH = sb + OFF_BH + (u32)((wn*16 + b_n) * WPITCH + b_kb);
    const u32 bAddrL = bAddrH + ABYT;

    float acc[2][2][4];
    #pragma unroll
    for (int i = 0; i < 2; i++)
        #pragma unroll
        for (int j = 0; j < 2; j++)
            #pragma unroll
            for (int v = 0; v < 4; v++) acc[i][j][v] = 0.0f;

    const int nst = K >> 5;

    auto load_stage = [&](int s) {
        const u32 base = sb + (u32)((s % 3) * STAGE);
        const int kt = s << 5;
        {
            int i = tid;
            int r = i >> 2, ch = i & 3;
            u32 d = base + (u32)(r * WPITCH + ch * 16);
            long g = (brow + r) * (long)K + kt + ch * 8;
            cp16(d, Ah + g);
            cp16(d + OFF_AL, Al + g);
            long gb = (long)r * K + kt + ch * 8;
            cp16(d + OFF_BH, Bh + gb);
            cp16(d + OFF_BL, Bl + gb);
        }
        cp_commit();
    };

    load_stage(0);
    load_stage(1);

    for (int s = 0; s < nst; s++) {
        if (s + 1 < nst) asm volatile("cp.async.wait_group 1;" ::: "memory");
        else             asm volatile("cp.async.wait_group 0;" ::: "memory");
        __syncthreads();
        if (s + 2 < nst) load_stage(s + 2);

        const u32 boff = (u32)((s % 3) * STAGE);
        #pragma unroll
        for (int kk = 0; kk < 2; kk++) {
            const u32 kadd = kk * 32;
            u32 bh[4], bl[4];
            ldsm4(bh, bAddrH + boff + kadd);
            ldsm4(bl, bAddrL + boff + kadd);
            #pragma unroll
            for (int mt = 0; mt < 2; mt++) {
                u32 ah[4], al[4];
                ldsm4(ah, aAddrH + boff + kadd + (u32)(mt*16*WPITCH));
                ldsm4(al, aAddrL + boff + kadd + (u32)(mt*16*WPITCH));
                #pragma unroll
                for (int nt = 0; nt < 2; nt++) {
                    mma_bf16(acc[mt][nt], ah, bh[2*nt], bh[2*nt+1]);
                    mma_bf16(acc[mt][nt], ah, bl[2*nt], bl[2*nt+1]);
                    mma_bf16(acc[mt][nt], al, bh[2*nt], bh[2*nt+1]);
                }
            }
        }
    }

    #pragma unroll
    for (int mt = 0; mt < 2; mt++) {
        long r0 = brow + wm*32 + mt*16 + (lane >> 2);
        long cc = wn*16 + ((lane & 3) << 1);
        #pragma unroll
        for (int nt = 0; nt < 2; nt++) {
            float2 v0 = make_float2(acc[mt][nt][0], acc[mt][nt][1]);
            float2 v1 = make_float2(acc[mt][nt][2], acc[mt][nt][3]);
            *(float2*)&C[r0 * N + cc + nt*8]     = v0;
            *(float2*)&C[(r0+8) * N + cc + nt*8] = v1;
        }
    }
}

// ---------------- operand prep kernels ----------------
__global__ __launch_bounds__(256) void convert_f16(
    const float* __restrict__ src, __half* __restrict__ dst, int n)
{
    int i = blockIdx.x * 256 + threadIdx.x;
    if (i < n) dst[i] = __float2half_rn(src[i]);
}

__global__ void transpose_f16(
    const float* __restrict__ src, __half* __restrict__ dst, int R, int C)
{
    __shared__ float t[32][33];
    int c0 = blockIdx.x * 32, r0 = blockIdx.y * 32;
    int tx = threadIdx.x, ty = threadIdx.y;
    #pragma unroll
    for (int i = 0; i < 32; i += 8)
        t[ty + i][tx] = src[(long)(r0 + ty + i) * C + c0 + tx];
    __syncthreads();
    #pragma unroll
    for (int i = 0; i < 32; i += 8)
        dst[(long)(c0 + ty + i) * R + r0 + tx] = __float2half_rn(t[tx][ty + i]);
}

__global__ void transpose_split_bf16(
    const float* __restrict__ src, bf16* __restrict__ hi, bf16* __restrict__ lo,
    int R, int C, int Cpad)
{
    __shared__ float t[32][33];
    int c0 = blockIdx.x * 32, r0 = blockIdx.y * 32;
    int tx = threadIdx.x, ty = threadIdx.y;
    #pragma unroll
    for (int i = 0; i < 32; i += 8) {
        int c = c0 + tx;
        float v = (c < C) ? src[(long)(r0 + ty + i) * C + c] : 0.0f;
        t[ty + i][tx] = v;
    }
    __syncthreads();
    #pragma unroll
    for (int i = 0; i < 32; i += 8) {
        int oc = c0 + ty + i;
        if (oc < Cpad) {
            float v = t[tx][ty + i];
            bf16 h = __float2bfloat16_rn(v);
            hi[(long)oc * R + r0 + tx] = h;
            lo[(long)oc * R + r0 + tx] = __float2bfloat16_rn(v - __bfloat162float(h));
        }
    }
}

// ---------------- tiled depthwise causal conv (K=4) + SiLU ----------------
#define CONV_TL 32
__global__ __launch_bounds__(256) void conv_silu_tiled(
    const __half* __restrict__ xz, const float* __restrict__ conv_w,
    const float* __restrict__ conv_b,
    bf16* __restrict__ xch, bf16* __restrict__ xcl)
{
    __shared__ float sx[CONV_TL + 3][256];
    const int tid = threadIdx.x;
    const int d0 = blockIdx.x * 256;
    const int l0 = blockIdx.y * CONV_TL;
    const int b  = blockIdx.z;
    const int d  = d0 + tid;

    #pragma unroll 5
    for (int r = 0; r < CONV_TL + 3; r++) {
        int l = l0 - 3 + r;
        sx[r][tid] = (l >= 0) ? __half2float(xz[((long)(b * LL + l)) * (2*DINNER) + d]) : 0.0f;
    }
    __syncthreads();

    const float4 wv = *(const float4*)&conv_w[d * DCONV];
    const float bias = conv_b[d];

    #pragma unroll 4
    for (int j = 0; j < CONV_TL; j++) {
        float acc = bias;
        acc += sx[j+0][tid] * wv.x;
        acc += sx[j+1][tid] * wv.y;
        acc += sx[j+2][tid] * wv.z;
        acc += sx[j+3][tid] * wv.w;
        float s = acc / (1.0f + __expf(-acc));
        long idx = ((long)(b * LL + l0 + j)) * DINNER + d;
        bf16 h = __float2bfloat16_rn(s);
        xch[idx] = h;
        xcl[idx] = __float2bfloat16_rn(s - __bfloat162float(h));
    }
}

// ---------------- coefficients + per-chunk a-products ----------------
__global__ __launch_bounds__(256) void coef_ptot(
    const float* __restrict__ xdbl, const float* __restrict__ A_log,
    float* __restrict__ coef, float* __restrict__ ptot)
{
    __shared__ float sa[CHL][16];
    const int c = blockIdx.x, b = blockIdx.y, tid = threadIdx.x;
    const int n = tid & 15;
    const long lbase = (long)b * LL + c * CHL;
    const float Aneg = -expf(A_log[n]);

    for (int r0 = 0; r0 < CHL; r0 += 16) {
        int rloc = r0 + (tid >> 4);
        long r = lbase + rloc;
        const float* xr = xdbl + r * 64;
        float v = xr[0];
        float delta = (v > 20.0f) ? v : log1pf(expf(v));
        float abar = expf(delta * Aneg);
        float* o = coef + r * 48;
        o[n]      = abar;
        o[16 + n] = delta * xr[1 + n];
        o[32 + n] = xr[17 + n];
        sa[rloc][n] = abar;
    }
    __syncthreads();
    if (tid < 16) {
        float p = 1.0f;
        #pragma unroll 8
        for (int l = 0; l < CHL; l++) p *= sa[l][tid];
        ptot[(b*NCH + c)*16 + tid] = p;
    }
}

// ---------------- scan pass 1 ----------------
__global__ __launch_bounds__(256) void scan_pass1(
    const float* __restrict__ coef, const bf16* __restrict__ xch,
    const bf16* __restrict__ xcl, float* __restrict__ hend)
{
    __shared__ float sca[CHL*32];
    int b = blockIdx.z, c = blockIdx.y, tid = threadIdx.x;
    int d = blockIdx.x * 256 + tid;
    long lbase = (long)b * LL + c * CHL;
    for (int i = tid; i < CHL*32; i += 256) {
        int row = i >> 5, j = i & 31;
        sca[i] = coef[(lbase + row)*48 + j];
    }
    __syncthreads();
    u64 h2[8];
    #pragma unroll
    for (int j = 0; j < 8; j++) h2[j] = 0ull;
    for (int l = 0; l < CHL; l++) {
        long ix = (lbase + l)*DINNER + d;
        float xv = __bfloat162float(xch[ix]) + __bfloat162float(xcl[ix]);
        u64 xx = pk2(xv, xv);
        const u64* ap = (const u64*)&sca[l*32];
        #pragma unroll
        for (int j = 0; j < 8; j++) {
            u64 u = mul2(ap[8+j], xx);
            h2[j] = fma2(ap[j], h2[j], u);
        }
    }
    float* o = hend + (((long)(b*NCH + c) * DINNER) + d) * 16;
    #pragma unroll
    for (int j = 0; j < 8; j++) {
        float x0, x1; up2(x0, x1, h2[j]);
        o[2*j] = x0; o[2*j+1] = x1;
    }
}

// ---------------- scan pass 2 ----------------
__global__ __launch_bounds__(256) void scan_pass2(
    const float* __restrict__ hend, const float* __restrict__ ptot,
    float* __restrict__ hstart)
{
    long idx = (long)blockIdx.x * 256 + threadIdx.x;
    int n = (int)(idx & 15);
    int d = (int)((idx >> 4) & (DINNER-1));
    int b = (int)(idx >> 15);
    float hs = 0.0f;
    for (int c = 0; c < NCH; c++) {
        long o = (((long)(b*NCH + c) * DINNER) + d) * 16 + n;
        hstart[o] = hs;
        hs = ptot[(b*NCH + c)*16 + n] * hs + hend[o];
    }
}

// ---------------- scan pass 3 ----------------
__global__ __launch_bounds__(256) void scan_pass3(
    const float* __restrict__ coef, const float* __restrict__ hstart,
    const bf16* __restrict__ xch, const bf16* __restrict__ xcl,
    const __half* __restrict__ xz, const float* __restrict__ Dp,
    __half* __restrict__ yh)
{
    __shared__ float sc[CHL*48];
    int b = blockIdx.z, c = blockIdx.y, tid = threadIdx.x;
    int d = blockIdx.x * 256 + tid;
    long lbase = (long)b * LL + c * CHL;
    for (int i = tid; i < CHL*48; i += 256)
        sc[i] = coef[lbase*48 + i];
    __syncthreads();

    u64 h2[8];
    const u64* hsp = (const u64*)(hstart + (((long)(b*NCH + c) * DINNER) + d) * 16);
    #pragma unroll
    for (int j = 0; j < 8; j++) h2[j] = hsp[j];
    float Dd = Dp[d];

    for (int l = 0; l < CHL; l++) {
        long row = lbase + l;
        long ix = row*DINNER + d;
        float xv = __bfloat162float(xch[ix]) + __bfloat162float(xcl[ix]);
        float zv = __half2float(xz[row*(2*DINNER) + DINNER + d]);
        u64 xx = pk2(xv, xv);
        const u64* ap = (const u64*)&sc[l*48];
        u64 y2 = 0ull;
        #pragma unroll
        for (int j = 0; j < 8; j++) {
            u64 u = mul2(ap[8+j], xx);
            h2[j] = fma2(ap[j], h2[j], u);
            y2 = fma2(h2[j], ap[16+j], y2);
        }
        float y0, y1;
        up2(y0, y1, y2);
        float y = y0 + y1 + xv * Dd;
        float sg = zv / (1.0f + __expf(-zv));
        yh[ix] = __float2half_rn(y * sg);
    }
}

// ---------------- launch ----------------
extern "C" void kernel_launch(void* const* d_in, const int* in_sizes, int n_in,
                              void* d_out, int out_size)
{
    const float* x       = (const float*)d_in[0];
    const float* W_in    = (const float*)d_in[1];
    const float* conv_w  = (const float*)d_in[2];
    const float* conv_b  = (const float*)d_in[3];
    const float* W_x     = (const float*)d_in[4];
    const float* A_log   = (const float*)d_in[5];
    const float* D_param = (const float*)d_in[6];
    const float* W_out   = (const float*)d_in[7];
    float* out = (float*)d_out;

    float *coefp, *xdbl, *ptot, *hend, *hstart;
    __half *xzh, *xh, *winT, *woutT, *yh;
    bf16 *xch, *xcl, *wxh, *wxl;
    cudaGetSymbolAddress((void**)&xzh,   g_xzh);
    cudaGetSymbolAddress((void**)&coefp, g_coef);
    cudaGetSymbolAddress((void**)&xdbl,  g_xdbl);
    cudaGetSymbolAddress((void**)&ptot,  g_ptot);
    cudaGetSymbolAddress((void**)&hend,  g_hend);
    cudaGetSymbolAddress((void**)&hstart,g_hstart);
    cudaGetSymbolAddress((void**)&xh,    g_xh);
    cudaGetSymbolAddress((void**)&winT,  g_winT);
    cudaGetSymbolAddress((void**)&woutT, g_woutT);
    cudaGetSymbolAddress((void**)&xch,   g_xch);
    cudaGetSymbolAddress((void**)&xcl,   g_xcl);
    cudaGetSymbolAddress((void**)&wxh,   g_wxT_h);
    cudaGetSymbolAddress((void**)&wxl,   g_wxT_l);
    cudaGetSymbolAddress((void**)&yh,    g_yh);

    const int SMEM1 = 3 * (2*128*PITCH);         // 110592
    const int SMEMW = 3 * (4*64*WPITCH);         // 61440
    cudaFuncSetAttribute((const void*)gemm_f16<__half>, cudaFuncAttributeMaxDynamicSharedMemorySize, SMEM1);
    cudaFuncSetAttribute((const void*)gemm_f16<float>,  cudaFuncAttributeMaxDynamicSharedMemorySize, SMEM1);
    cudaFuncSetAttribute((const void*)gemm_wx64,        cudaFuncAttributeMaxDynamicSharedMemorySize, SMEMW);

    // 1) x -> fp16
    convert_f16<<<(M_ROWS*DMODEL)/256, 256>>>(x, xh, M_ROWS*DMODEL);
    // 2) W_in^T fp16
    transpose_f16<<<dim3(4096/32, 1024/32), dim3(32,8)>>>(W_in, winT, 1024, 4096);
    // 3) W_x^T bf16 split
    transpose_split_bf16<<<dim3(64/32, 2048/32), dim3(32,8)>>>(W_x, wxh, wxl, 2048, 33, 64);
    // 4) GEMM1: xz(fp16) = x @ W_in                      <-- profiled slot
    gemm_f16<__half><<<dim3(4096/128, 8192/128), 256, SMEM1>>>(
        (const u16*)xh, (const u16*)winT, xzh, 4096, 1024);
    // 5) W_out^T fp16
    transpose_f16<<<dim3(1024/32, 2048/32), dim3(32,8)>>>(W_out, woutT, 2048, 1024);
    // 6) conv + silu -> bf16 split
    conv_silu_tiled<<<dim3(DINNER/256, LL/CONV_TL, BB), 256>>>(
        xzh, conv_w, conv_b, xch, xcl);
    // 7) x_dbl = xc @ W_x
    gemm_wx64<<<dim3(1, 8192/64), 256, SMEMW>>>(
        (const u16*)xch, (const u16*)xcl, (const u16*)wxh, (const u16*)wxl, xdbl, 64, 2048);
    // 8) coefficients + chunk products
    coef_ptot<<<dim3(NCH, BB), 256>>>(xdbl, A_log, coefp, ptot);
    // 9-11) chunked parallel scan
    scan_pass1<<<dim3(DINNER/256, NCH, BB), 256>>>(coefp, xch, xcl, hend);
    scan_pass2<<<(BB*DINNER*DSTATE)/256, 256>>>(hend, ptot, hstart);
    scan_pass3<<<dim3(DINNER/256, NCH, BB), 256>>>(coefp, hstart, xch, xcl, xzh, D_param, yh);
    // 12) out = y @ W_out
    gemm_f16<float><<<dim3(1024/128, 8192/128), 256, SMEM1>>>(
        (const u16*)yh, (const u16*)woutT, out, 1024, 2048);
}